// round 1
// baseline (speedup 1.0000x reference)
#include <cuda_runtime.h>
#include <math.h>

// Problem constants
#define Bb 32
#define Tt 8
#define Nn 150
#define Ff 16
#define Hh 32
#define Rr 4
#define Ee 16

#define HSZ (Bb*Nn*Hh*Rr)          // 614400 floats per hidden buffer
#define XHF_SZ (4*Nn*Bb*64)        // 1228800, max C = 64
#define GF_SZ (4*Nn*Bb*Hh)         // 614400

// Frequency-slot convention everywhere: 0 = f0 (real), 1 = Re(f1), 2 = Im(f1), 3 = f2 (real)

__device__ float g_Af[4*Nn*Nn];          // adjacency, freq slots
__device__ float g_W[2*3*4*64*32];       // combined [layer][gate z/r/h][slot][c(<=64)][h]
__device__ float g_XHf[XHF_SZ];          // fft of [X | Hs], layout [s][n][b*C+c]
__device__ float g_AXH[XHF_SZ];          // Af @ XHf
__device__ float g_Gf[GF_SZ];            // fft of Rg*Hs, layout [s][n][b*H+h]
__device__ float g_AG[GF_SZ];            // Af @ Gf
__device__ float g_Z[HSZ];               // update gate, real domain [b][n][h][r]
__device__ float g_H[4][HSZ];            // H0a,H0b,H1a,H1b

// ---------------------------------------------------------------------------
// Adjacency precompute: A = ifft(Uf Uf^T).real -> relu -> softmax(axis=m) -> fft
// One block per n (256 threads, thread = m).
// ---------------------------------------------------------------------------
__global__ void adj_kernel(const float* __restrict__ U) {
    __shared__ float sUf[Ee][4];
    __shared__ float red[256];
    int n = blockIdx.x;
    int tid = threadIdx.x;
    if (tid < Ee*4) {
        int e = tid >> 2, s = tid & 3;
        const float* p = U + (n*Ee + e)*4;
        float u0=p[0],u1=p[1],u2=p[2],u3=p[3];
        float v;
        if (s==0) v = u0+u1+u2+u3;
        else if (s==1) v = u0-u2;
        else if (s==2) v = u3-u1;
        else v = u0-u1+u2-u3;
        sUf[e][s] = v;
    }
    __syncthreads();
    int m = tid;
    float a0=0.f,a1=0.f,a2=0.f,a3=0.f;
    if (m < Nn) {
        float P0=0.f,P1r=0.f,P1i=0.f,P2=0.f;
        #pragma unroll
        for (int e=0;e<Ee;e++){
            const float* p = U + (m*Ee + e)*4;
            float u0=p[0],u1=p[1],u2=p[2],u3=p[3];
            float m0=u0+u1+u2+u3, m1r=u0-u2, m1i=u3-u1, m2=u0-u1+u2-u3;
            float q0=sUf[e][0], q1r=sUf[e][1], q1i=sUf[e][2], q2=sUf[e][3];
            P0  += q0*m0;
            P2  += q2*m2;
            P1r += q1r*m1r - q1i*m1i;   // complex product, NO conjugate (matches einsum)
            P1i += q1r*m1i + q1i*m1r;
        }
        a0 = fmaxf(0.25f*(P0 + P2 + 2.f*P1r), 0.f);
        a1 = fmaxf(0.25f*(P0 - P2 - 2.f*P1i), 0.f);
        a2 = fmaxf(0.25f*(P0 + P2 - 2.f*P1r), 0.f);
        a3 = fmaxf(0.25f*(P0 - P2 + 2.f*P1i), 0.f);
    }
    float av[4] = {a0,a1,a2,a3};
    float v[4];
    for (int r=0;r<4;r++){
        red[tid] = (m<Nn) ? av[r] : -1e30f; __syncthreads();
        for (int s=128;s>0;s>>=1){ if (tid<s) red[tid]=fmaxf(red[tid],red[tid+s]); __syncthreads(); }
        float mx = red[0]; __syncthreads();
        float ex = (m<Nn) ? expf(av[r]-mx) : 0.f;
        red[tid] = ex; __syncthreads();
        for (int s=128;s>0;s>>=1){ if (tid<s) red[tid]+=red[tid+s]; __syncthreads(); }
        float sm = red[0]; __syncthreads();
        v[r] = ex / sm;
    }
    if (m < Nn) {
        g_Af[0*Nn*Nn + n*Nn + m] = v[0]+v[1]+v[2]+v[3];
        g_Af[1*Nn*Nn + n*Nn + m] = v[0]-v[2];
        g_Af[2*Nn*Nn + n*Nn + m] = v[3]-v[1];
        g_Af[3*Nn*Nn + n*Nn + m] = v[0]-v[1]+v[2]-v[3];
    }
}

// ---------------------------------------------------------------------------
// Weight precompute: combined [Wx ; Wh] per gate, fft over relation axis.
// gate 0 = z: [Wxz;Whz], gate 1 = r: [Wxr;Whr], gate 2 = h: [Wxh;Whr]
// ---------------------------------------------------------------------------
__global__ void wprep_kernel(const float* wxz0,const float* wxr0,const float* wxh0,
                             const float* whz0,const float* whr0,
                             const float* wxz1,const float* wxr1,const float* wxh1,
                             const float* whz1,const float* whr1) {
    int idx = blockIdx.x*blockDim.x + threadIdx.x;
    if (idx >= 2*3*64*32) return;
    int h = idx & 31;
    int c = (idx >> 5) & 63;
    int g = (idx >> 11) % 3;
    int l = idx / (3*64*32);
    int Fin = l ? 32 : 16;
    int C = Fin + 32;
    float w[4] = {0.f,0.f,0.f,0.f};
    if (c < C) {
        bool xp = c < Fin;
        int row = xp ? c : (c - Fin);
        const float* src;
        if (l == 0)
            src = (g==0) ? (xp? wxz0: whz0) : (g==1) ? (xp? wxr0: whr0) : (xp? wxh0: whr0);
        else
            src = (g==0) ? (xp? wxz1: whz1) : (g==1) ? (xp? wxr1: whr1) : (xp? wxh1: whr1);
        const float* p = src + (row*Hh + h)*4;
        float u0=p[0],u1=p[1],u2=p[2],u3=p[3];
        w[0]=u0+u1+u2+u3; w[1]=u0-u2; w[2]=u3-u1; w[3]=u0-u1+u2-u3;
    }
    int base = ((l*3+g)*4)*2048 + c*32 + h;
    #pragma unroll
    for (int s=0;s<4;s++) g_W[base + s*2048] = w[s];
}

// ---------------------------------------------------------------------------
// K1: fft of [X | Hs] along relation axis -> g_XHf [s][n][b*C+c]
// ---------------------------------------------------------------------------
__global__ void fft_kernel(const float* __restrict__ xsrc, int bStrideX, int nStrideX,
                           const float* __restrict__ hsrc, int C, int Fin) {
    int J = Bb * C;
    int total = Bb*Nn*C;
    for (int idx = blockIdx.x*blockDim.x + threadIdx.x; idx < total; idx += gridDim.x*blockDim.x) {
        int c = idx % C;
        int n = (idx / C) % Nn;
        int b = idx / (C*Nn);
        float x0,x1,x2,x3;
        if (c < Fin) {
            const float4 vv = *reinterpret_cast<const float4*>(xsrc + (size_t)b*bStrideX + (size_t)n*nStrideX + c*4);
            x0=vv.x; x1=vv.y; x2=vv.z; x3=vv.w;
        } else if (hsrc) {
            const float4 vv = *reinterpret_cast<const float4*>(hsrc + (((size_t)b*Nn + n)*Hh + (c-Fin))*4);
            x0=vv.x; x1=vv.y; x2=vv.z; x3=vv.w;
        } else { x0=x1=x2=x3=0.f; }
        int base = n*J + b*C + c;
        g_XHf[0*Nn*J + base] = x0+x1+x2+x3;
        g_XHf[1*Nn*J + base] = x0-x2;
        g_XHf[2*Nn*J + base] = x3-x1;
        g_XHf[3*Nn*J + base] = x0-x1+x2-x3;
    }
}

// ---------------------------------------------------------------------------
// K2/K4: node aggregation GEMM per freq slot. Out[cs][n][j] with complex combos:
// cs0: A0@X0 ; cs1: A1r@X1r - A1i@X1i ; cs2: A1r@X1i + A1i@X1r ; cs3: A2@X2
// Block tile 32(n) x 64(j), 16x16 threads, each 2x4 outputs. K=150 in chunks of 32.
// ---------------------------------------------------------------------------
__global__ void agg_gemm(const float* __restrict__ Xf, float* __restrict__ Out, int J) {
    const int cs = blockIdx.z;
    const int tA0c[4] = {0,1,1,3};
    const int tA1c[4] = {0,2,2,3};
    const int tX0c[4] = {0,1,2,3};
    const int tX1c[4] = {0,2,1,3};
    const bool dual = (cs==1 || cs==2);
    const float sgn = (cs==1) ? -1.f : 1.f;
    __shared__ float sA[2][32][33];
    __shared__ float sB[2][32][64];
    int tid = threadIdx.y*16 + threadIdx.x;
    int nBase = blockIdx.y*32, jBase = blockIdx.x*64;
    float acc[2][4] = {{0.f,0.f,0.f,0.f},{0.f,0.f,0.f,0.f}};
    const float* A0p = g_Af + tA0c[cs]*Nn*Nn;
    const float* A1p = g_Af + tA1c[cs]*Nn*Nn;
    const float* X0p = Xf + (size_t)tX0c[cs]*Nn*J;
    const float* X1p = Xf + (size_t)tX1c[cs]*Nn*J;

    for (int k0=0; k0<Nn; k0+=32) {
        for (int i=tid;i<1024;i+=256){
            int rr=i>>5, cc=i&31; int nn=nBase+rr, kk=k0+cc;
            float v0=0.f,v1=0.f;
            if (nn<Nn && kk<Nn){ v0=A0p[nn*Nn+kk]; if (dual) v1=A1p[nn*Nn+kk]; }
            sA[0][rr][cc]=v0; sA[1][rr][cc]=v1;
        }
        for (int i=tid;i<2048;i+=256){
            int rr=i>>6, cc=i&63; int kk=k0+rr;
            float v0=0.f,v1=0.f;
            if (kk<Nn){ int off=kk*J + jBase+cc; v0=X0p[off]; if (dual) v1=X1p[off]; }
            sB[0][rr][cc]=v0; sB[1][rr][cc]=v1;
        }
        __syncthreads();
        if (dual) {
            #pragma unroll
            for (int kk=0;kk<32;kk++){
                float a00=sA[0][threadIdx.y*2  ][kk];
                float a01=sA[0][threadIdx.y*2+1][kk];
                float a10=sgn*sA[1][threadIdx.y*2  ][kk];
                float a11=sgn*sA[1][threadIdx.y*2+1][kk];
                #pragma unroll
                for (int jj=0;jj<4;jj++){
                    float b0=sB[0][kk][threadIdx.x*4+jj];
                    float b1=sB[1][kk][threadIdx.x*4+jj];
                    acc[0][jj] += a00*b0 + a10*b1;
                    acc[1][jj] += a01*b0 + a11*b1;
                }
            }
        } else {
            #pragma unroll
            for (int kk=0;kk<32;kk++){
                float a00=sA[0][threadIdx.y*2  ][kk];
                float a01=sA[0][threadIdx.y*2+1][kk];
                #pragma unroll
                for (int jj=0;jj<4;jj++){
                    float b0=sB[0][kk][threadIdx.x*4+jj];
                    acc[0][jj] += a00*b0;
                    acc[1][jj] += a01*b0;
                }
            }
        }
        __syncthreads();
    }
    float* Op = Out + (size_t)cs*Nn*J;
    #pragma unroll
    for (int i=0;i<2;i++){
        int nn = nBase + threadIdx.y*2 + i;
        if (nn<Nn){
            #pragma unroll
            for (int jj=0;jj<4;jj++)
                Op[nn*J + jBase + threadIdx.x*4 + jj] = acc[i][jj];
        }
    }
}

// ---------------------------------------------------------------------------
// K3: gates Z, Rg = sigmoid(ifft([AX|AH]@[Wx;Wh]) + b); G = Rg*Hs; store Z, fft(G)
// Block = (n, 8 batches), threads (h=32, b=8).
// ---------------------------------------------------------------------------
__global__ void gates_kernel(const float* __restrict__ Hs, const float* __restrict__ bias,
                             int wbase, int C) {
    int J = Bb*C;
    __shared__ float sX[8][4][64];
    int n = blockIdx.x, bBase = blockIdx.y*8;
    int tid = threadIdx.y*32 + threadIdx.x;
    int tot = 8*4*C;
    for (int i=tid;i<tot;i+=256){
        int bl = i/(4*C); int rem = i - bl*4*C; int s = rem / C; int c = rem % C;
        sX[bl][s][c] = g_AXH[(size_t)s*Nn*J + n*J + (bBase+bl)*C + c];
    }
    __syncthreads();
    int h = threadIdx.x, bl = threadIdx.y, b = bBase + bl;
    const float* Wz = g_W + wbase;
    const float* Wr = g_W + wbase + 4*2048;
    float yz0=0,yz1r=0,yz1i=0,yz2=0, yr0=0,yr1r=0,yr1i=0,yr2=0;
    for (int c=0;c<C;c++){
        float x0=sX[bl][0][c], x1r=sX[bl][1][c], x1i=sX[bl][2][c], x2=sX[bl][3][c];
        int wo = c*32 + h;
        float w0=Wz[wo], w1=Wz[2048+wo], w2=Wz[2*2048+wo], w3=Wz[3*2048+wo];
        yz0 += x0*w0; yz1r += x1r*w1 - x1i*w2; yz1i += x1r*w2 + x1i*w1; yz2 += x2*w3;
        w0=Wr[wo]; w1=Wr[2048+wo]; w2=Wr[2*2048+wo]; w3=Wr[3*2048+wo];
        yr0 += x0*w0; yr1r += x1r*w1 - x1i*w2; yr1i += x1r*w2 + x1i*w1; yr2 += x2*w3;
    }
    float vz[4] = {0.25f*(yz0+yz2+2.f*yz1r), 0.25f*(yz0-yz2-2.f*yz1i),
                   0.25f*(yz0+yz2-2.f*yz1r), 0.25f*(yz0-yz2+2.f*yz1i)};
    float vr[4] = {0.25f*(yr0+yr2+2.f*yr1r), 0.25f*(yr0-yr2-2.f*yr1i),
                   0.25f*(yr0+yr2-2.f*yr1r), 0.25f*(yr0-yr2+2.f*yr1i)};
    size_t hoff = (((size_t)b*Nn + n)*Hh + h)*4;
    float g[4];
    #pragma unroll
    for (int r=0;r<4;r++){
        float z  = 1.f/(1.f+expf(-(vz[r] + bias[0*128 + h*4 + r])));
        float rg = 1.f/(1.f+expf(-(vr[r] + bias[1*128 + h*4 + r])));
        float hs = Hs ? Hs[hoff + r] : 0.f;
        g[r] = rg*hs;
        g_Z[hoff + r] = z;
    }
    int gbase = n*(Bb*Hh) + b*Hh + h;
    g_Gf[0*Nn*Bb*Hh + gbase] = g[0]+g[1]+g[2]+g[3];
    g_Gf[1*Nn*Bb*Hh + gbase] = g[0]-g[2];
    g_Gf[2*Nn*Bb*Hh + gbase] = g[3]-g[1];
    g_Gf[3*Nn*Bb*Hh + gbase] = g[0]-g[1]+g[2]-g[3];
}

// ---------------------------------------------------------------------------
// K5: Ht = tanh(ifft([AX|AG]@[Wxh;Whr]) + bh); Hnew = Z*Hs + (1-Z)*Ht
// ---------------------------------------------------------------------------
__global__ void ht_kernel(const float* __restrict__ Hs, const float* __restrict__ bias,
                          int wbase, int C, int Fin, float* __restrict__ Hnew,
                          float* __restrict__ outp, int t, float* __restrict__ tailp) {
    int J = Bb*C;
    __shared__ float sXx[8][4][32];
    __shared__ float sG[8][4][32];
    int n = blockIdx.x, bBase = blockIdx.y*8;
    int tid = threadIdx.y*32 + threadIdx.x;
    int tot1 = 8*4*Fin;
    for (int i=tid;i<tot1;i+=256){
        int bl=i/(4*Fin); int rem=i-bl*4*Fin; int s=rem/Fin; int c=rem%Fin;
        sXx[bl][s][c] = g_AXH[(size_t)s*Nn*J + n*J + (bBase+bl)*C + c];
    }
    for (int i=tid;i<8*4*32;i+=256){
        int bl=i>>7; int rem=i&127; int s=rem>>5; int c=rem&31;
        sG[bl][s][c] = g_AG[(size_t)s*Nn*Bb*Hh + n*Bb*Hh + (bBase+bl)*Hh + c];
    }
    __syncthreads();
    int h=threadIdx.x, bl=threadIdx.y, b=bBase+bl;
    const float* Wh = g_W + wbase;
    float y0=0,y1r=0,y1i=0,y2=0;
    for (int c=0;c<Fin;c++){
        float x0=sXx[bl][0][c],x1r=sXx[bl][1][c],x1i=sXx[bl][2][c],x2=sXx[bl][3][c];
        int wo=c*32+h;
        float w0=Wh[wo],w1=Wh[2048+wo],w2=Wh[2*2048+wo],w3=Wh[3*2048+wo];
        y0+=x0*w0; y1r+=x1r*w1-x1i*w2; y1i+=x1r*w2+x1i*w1; y2+=x2*w3;
    }
    for (int c=0;c<Hh;c++){
        float x0=sG[bl][0][c],x1r=sG[bl][1][c],x1i=sG[bl][2][c],x2=sG[bl][3][c];
        int wo=(Fin+c)*32+h;
        float w0=Wh[wo],w1=Wh[2048+wo],w2=Wh[2*2048+wo],w3=Wh[3*2048+wo];
        y0+=x0*w0; y1r+=x1r*w1-x1i*w2; y1i+=x1r*w2+x1i*w1; y2+=x2*w3;
    }
    float v[4] = {0.25f*(y0+y2+2.f*y1r), 0.25f*(y0-y2-2.f*y1i),
                  0.25f*(y0+y2-2.f*y1r), 0.25f*(y0-y2+2.f*y1i)};
    size_t hoff = (((size_t)b*Nn+n)*Hh + h)*4;
    #pragma unroll
    for (int r=0;r<4;r++){
        float ht = tanhf(v[r] + bias[2*128 + h*4 + r]);
        float z  = g_Z[hoff+r];
        float hs = Hs ? Hs[hoff+r] : 0.f;
        float hn = z*hs + (1.f-z)*ht;
        Hnew[hoff+r] = hn;
        if (outp)  outp[(((size_t)b*Tt + t)*Nn + n)*(Hh*4) + h*4 + r] = hn;
        if (tailp) tailp[hoff+r] = hn;
    }
}

// ---------------------------------------------------------------------------
// Host orchestration
// ---------------------------------------------------------------------------
extern "C" void kernel_launch(void* const* d_in, const int* in_sizes, int n_in,
                              void* d_out, int out_size) {
    (void)in_sizes; (void)n_in;
    const float* inputs = (const float*)d_in[0];
    const float* U      = (const float*)d_in[1];
    const float* B0p    = (const float*)d_in[7];
    const float* B1p    = (const float*)d_in[13];
    float* out = (float*)d_out;
    const int OUTSZ = Bb*Tt*Nn*Hh*Rr;
    float* tail = (out_size >= OUTSZ + 2*HSZ) ? (out + OUTSZ) : nullptr;

    adj_kernel<<<Nn, 256>>>(U);
    wprep_kernel<<<48, 256>>>((const float*)d_in[2], (const float*)d_in[3], (const float*)d_in[4],
                              (const float*)d_in[5], (const float*)d_in[6],
                              (const float*)d_in[8], (const float*)d_in[9], (const float*)d_in[10],
                              (const float*)d_in[11], (const float*)d_in[12]);

    void* p;
    cudaGetSymbolAddress(&p, g_H);   float* Hbase = (float*)p;
    cudaGetSymbolAddress(&p, g_XHf); float* XHf   = (float*)p;
    cudaGetSymbolAddress(&p, g_AXH); float* AXH   = (float*)p;
    cudaGetSymbolAddress(&p, g_Gf);  float* Gf    = (float*)p;
    cudaGetSymbolAddress(&p, g_AG);  float* AG    = (float*)p;
    float* H0[2] = {Hbase,          Hbase +   HSZ};
    float* H1[2] = {Hbase + 2*HSZ,  Hbase + 3*HSZ};

    auto runCell = [&](int l, const float* xsrc, int bsx, int nsx, const float* Hs,
                       float* Hnew, const float* bias, float* outp, int t, float* tailp) {
        int Fin = l ? 32 : 16;
        int C = Fin + 32;
        int J = Bb*C;
        int tot = Bb*Nn*C;
        fft_kernel<<<(tot+255)/256, 256>>>(xsrc, bsx, nsx, Hs, C, Fin);
        agg_gemm<<<dim3(J/64, (Nn+31)/32, 4), dim3(16,16)>>>(XHf, AXH, J);
        gates_kernel<<<dim3(Nn, Bb/8), dim3(32,8)>>>(Hs, bias, (l*3+0)*4*2048, C);
        agg_gemm<<<dim3((Bb*Hh)/64, (Nn+31)/32, 4), dim3(16,16)>>>(Gf, AG, Bb*Hh);
        ht_kernel<<<dim3(Nn, Bb/8), dim3(32,8)>>>(Hs, bias, (l*3+2)*4*2048, C, Fin,
                                                  Hnew, outp, t, tailp);
    };

    // t = 0: layer1 consumes CURRENT layer0 output
    runCell(0, inputs, Tt*Nn*Ff*Rr, Ff*Rr, nullptr, H0[0], B0p, nullptr, 0, nullptr);
    runCell(1, H0[0], Nn*Hh*Rr, Hh*Rr, nullptr, H1[0], B1p, out, 0, nullptr);

    int c0 = 0, c1 = 0;
    for (int t=1; t<Tt; t++){
        float* tl0 = (t==Tt-1 && tail) ? tail        : nullptr;
        float* tl1 = (t==Tt-1 && tail) ? tail + HSZ  : nullptr;
        // layer0: new hidden from X_t and previous H0
        runCell(0, inputs + (size_t)t*Nn*Ff*Rr, Tt*Nn*Ff*Rr, Ff*Rr,
                H0[c0], H0[c0^1], B0p, nullptr, t, tl0);
        // layer1: consumes PREVIOUS timestep's layer0 output (H0[c0], pre-update)
        runCell(1, H0[c0], Nn*Hh*Rr, Hh*Rr,
                H1[c1], H1[c1^1], B1p, out, t, tl1);
        c0 ^= 1; c1 ^= 1;
    }
}

// round 2
// speedup vs baseline: 1.1855x; 1.1855x over previous
#include <cuda_runtime.h>
#include <math.h>

// Problem constants
#define Bb 32
#define Tt 8
#define Nn 150
#define Ff 16
#define Hh 32
#define Rr 4
#define Ee 16

#define NP 160                 // K dim padded (nodes as reduction axis)
#define NR 192                 // row dim padded (3 x 64 tiles)
#define JX 3584                // fixed col stride for XHf / AXH
#define JG 2048                // fixed col stride for Gf / AG
#define HSZ (Bb*Nn*Hh*Rr)      // 614400

// Frequency slots: 0 = f0 (real), 1 = Re(f1), 2 = Im(f1), 3 = f2 (real)

__device__ float g_At[4*NP*NR];     // adjacency, TRANSPOSED: At[s][k][n], zero-padded
__device__ float g_W[2*3*4*64*32];  // [layer][gate z/r/h][slot][c<=64][h]
__device__ float g_XHf[4*NP*JX];    // fft of inputs, [s][n(160)][col(JX)], pad rows zero
__device__ float g_AXH[4*Nn*JX];    // A @ XHf
__device__ float g_Gf[4*NP*JG];     // fft of Rg*Hs, [s][n(160)][col(JG)], pad rows zero
__device__ float g_AG[4*Nn*JG];     // A @ Gf
__device__ float g_Z[2*HSZ];        // update gates per layer
__device__ float g_H[4*HSZ];        // H0a,H0b,H1a,H1b

// ---------------------------------------------------------------------------
// Adjacency: A = ifft(Uf Uf^T).real -> relu -> softmax(axis=m) -> fft -> store
// transposed At[s][m][n] (m is the reduction index in the aggregation).
// ---------------------------------------------------------------------------
__global__ void adj_kernel(const float* __restrict__ U) {
    __shared__ float sUf[Ee][4];
    __shared__ float red[256];
    int n = blockIdx.x;
    int tid = threadIdx.x;
    if (tid < Ee*4) {
        int e = tid >> 2, s = tid & 3;
        const float* p = U + (n*Ee + e)*4;
        float u0=p[0],u1=p[1],u2=p[2],u3=p[3];
        float v;
        if (s==0) v = u0+u1+u2+u3;
        else if (s==1) v = u0-u2;
        else if (s==2) v = u3-u1;
        else v = u0-u1+u2-u3;
        sUf[e][s] = v;
    }
    __syncthreads();
    int m = tid;
    float a0=0.f,a1=0.f,a2=0.f,a3=0.f;
    if (m < Nn) {
        float P0=0.f,P1r=0.f,P1i=0.f,P2=0.f;
        #pragma unroll
        for (int e=0;e<Ee;e++){
            const float* p = U + (m*Ee + e)*4;
            float u0=p[0],u1=p[1],u2=p[2],u3=p[3];
            float m0=u0+u1+u2+u3, m1r=u0-u2, m1i=u3-u1, m2=u0-u1+u2-u3;
            float q0=sUf[e][0], q1r=sUf[e][1], q1i=sUf[e][2], q2=sUf[e][3];
            P0  += q0*m0;
            P2  += q2*m2;
            P1r += q1r*m1r - q1i*m1i;
            P1i += q1r*m1i + q1i*m1r;
        }
        a0 = fmaxf(0.25f*(P0 + P2 + 2.f*P1r), 0.f);
        a1 = fmaxf(0.25f*(P0 - P2 - 2.f*P1i), 0.f);
        a2 = fmaxf(0.25f*(P0 + P2 - 2.f*P1r), 0.f);
        a3 = fmaxf(0.25f*(P0 - P2 + 2.f*P1i), 0.f);
    }
    float av[4] = {a0,a1,a2,a3};
    float v[4];
    for (int r=0;r<4;r++){
        red[tid] = (m<Nn) ? av[r] : -1e30f; __syncthreads();
        for (int s=128;s>0;s>>=1){ if (tid<s) red[tid]=fmaxf(red[tid],red[tid+s]); __syncthreads(); }
        float mx = red[0]; __syncthreads();
        float ex = (m<Nn) ? expf(av[r]-mx) : 0.f;
        red[tid] = ex; __syncthreads();
        for (int s=128;s>0;s>>=1){ if (tid<s) red[tid]+=red[tid+s]; __syncthreads(); }
        float sm = red[0]; __syncthreads();
        v[r] = ex / sm;
    }
    if (m < Nn) {
        g_At[0*NP*NR + m*NR + n] = v[0]+v[1]+v[2]+v[3];
        g_At[1*NP*NR + m*NR + n] = v[0]-v[2];
        g_At[2*NP*NR + m*NR + n] = v[3]-v[1];
        g_At[3*NP*NR + m*NR + n] = v[0]-v[1]+v[2]-v[3];
    }
}

// ---------------------------------------------------------------------------
// Weight precompute: combined [Wx ; Wh] per gate, fft over relation axis.
// ---------------------------------------------------------------------------
__global__ void wprep_kernel(const float* wxz0,const float* wxr0,const float* wxh0,
                             const float* whz0,const float* whr0,
                             const float* wxz1,const float* wxr1,const float* wxh1,
                             const float* whz1,const float* whr1) {
    int idx = blockIdx.x*blockDim.x + threadIdx.x;
    if (idx >= 2*3*64*32) return;
    int h = idx & 31;
    int c = (idx >> 5) & 63;
    int g = (idx >> 11) % 3;
    int l = idx / (3*64*32);
    int Fin = l ? 32 : 16;
    int C = Fin + 32;
    float w[4] = {0.f,0.f,0.f,0.f};
    if (c < C) {
        bool xp = c < Fin;
        int row = xp ? c : (c - Fin);
        const float* src;
        if (l == 0)
            src = (g==0) ? (xp? wxz0: whz0) : (g==1) ? (xp? wxr0: whr0) : (xp? wxh0: whr0);
        else
            src = (g==0) ? (xp? wxz1: whz1) : (g==1) ? (xp? wxr1: whr1) : (xp? wxh1: whr1);
        const float* p = src + (row*Hh + h)*4;
        float u0=p[0],u1=p[1],u2=p[2],u3=p[3];
        w[0]=u0+u1+u2+u3; w[1]=u0-u2; w[2]=u3-u1; w[3]=u0-u1+u2-u3;
    }
    int base = ((l*3+g)*4)*2048 + c*32 + h;
    #pragma unroll
    for (int s=0;s<4;s++) g_W[base + s*2048] = w[s];
}

// ---------------------------------------------------------------------------
// fft of up to two column sections -> g_XHf [s][n][col] (stride JX)
// section layout: cols [0,colBase1) from (x0,h0,C0); [colBase1,J) from (x1,h1,C1)
// ---------------------------------------------------------------------------
__global__ void fft2_kernel(int J,
    const float* __restrict__ x0, int xb0, int xn0, const float* __restrict__ h0, int C0,
    const float* __restrict__ x1, int xb1, int xn1, const float* __restrict__ h1, int C1,
    int colBase1)
{
    int total = Nn*J;
    for (int idx = blockIdx.x*blockDim.x+threadIdx.x; idx < total; idx += gridDim.x*blockDim.x){
        int n = idx / J, col = idx - n*J;
        const float* xp; const float* hp; int xb,xn,C,q;
        if (col < colBase1){ q = col; C = C0; xp=x0; xb=xb0; xn=xn0; hp=h0; }
        else               { q = col-colBase1; C=C1; xp=x1; xb=xb1; xn=xn1; hp=h1; }
        int Fin = C - 32;
        int b = q / C, c = q - b*C;
        float v0,v1,v2,v3;
        if (c < Fin){
            const float4 vv = *reinterpret_cast<const float4*>(xp + (size_t)b*xb + (size_t)n*xn + c*4);
            v0=vv.x; v1=vv.y; v2=vv.z; v3=vv.w;
        } else if (hp){
            const float4 vv = *reinterpret_cast<const float4*>(hp + (((size_t)b*Nn+n)*Hh + (c-Fin))*4);
            v0=vv.x; v1=vv.y; v2=vv.z; v3=vv.w;
        } else { v0=v1=v2=v3=0.f; }
        size_t base = (size_t)n*JX + col;
        g_XHf[0*(size_t)NP*JX + base] = v0+v1+v2+v3;
        g_XHf[1*(size_t)NP*JX + base] = v0-v2;
        g_XHf[2*(size_t)NP*JX + base] = v3-v1;
        g_XHf[3*(size_t)NP*JX + base] = v0-v1+v2-v3;
    }
}

// ---------------------------------------------------------------------------
// Aggregation GEMM. grid (J/64, 3, 3), block (16,16). 64x64 tile, 4x4/thread.
// gz=0: out0 = A0@X0 ; gz=1: out1 = A1@X1 - A2@X2, out2 = A1@X2 + A2@X1 ;
// gz=2: out3 = A3@X3.  A is pre-transposed & zero-padded -> no bounds checks.
// ---------------------------------------------------------------------------
__global__ void agg2_kernel(const float* __restrict__ Xf, float* __restrict__ Out, int stride){
    int gz = blockIdx.z;
    bool dual = (gz==1);
    int s0 = (gz==0) ? 0 : ((gz==1) ? 1 : 3);
    const float* A0 = g_At + (size_t)s0*NP*NR;
    const float* A1 = g_At + (size_t)2*NP*NR;
    const float* X0 = Xf + (size_t)s0*NP*stride;
    const float* X1 = Xf + (size_t)2*NP*stride;
    float* O0 = Out + (size_t)s0*Nn*stride;
    float* O1 = Out + (size_t)2*Nn*stride;
    int nBase = blockIdx.y*64, jBase = blockIdx.x*64;

    __shared__ float sA[2][32][68];
    __shared__ float sB[2][32][64];
    int tx = threadIdx.x, ty = threadIdx.y;
    int tid = ty*16 + tx;
    float aRe[4][4] = {};
    float aIm[4][4] = {};

    for (int k0=0; k0<NP; k0+=32){
        __syncthreads();
        if (dual){
            #pragma unroll
            for (int i=tid;i<2048;i+=256){
                int a=i&63, kb=i>>6;
                sA[0][kb][a] = A0[(size_t)(k0+kb)*NR + nBase+a];
                sB[0][kb][a] = X0[(size_t)(k0+kb)*stride + jBase+a];
                sA[1][kb][a] = A1[(size_t)(k0+kb)*NR + nBase+a];
                sB[1][kb][a] = X1[(size_t)(k0+kb)*stride + jBase+a];
            }
        } else {
            #pragma unroll
            for (int i=tid;i<2048;i+=256){
                int a=i&63, kb=i>>6;
                sA[0][kb][a] = A0[(size_t)(k0+kb)*NR + nBase+a];
                sB[0][kb][a] = X0[(size_t)(k0+kb)*stride + jBase+a];
            }
        }
        __syncthreads();

        if (dual){
            #pragma unroll 8
            for (int kk=0;kk<32;kk++){
                float4 ar4 = *reinterpret_cast<const float4*>(&sA[0][kk][ty*4]);
                float4 ai4 = *reinterpret_cast<const float4*>(&sA[1][kk][ty*4]);
                float4 br4 = *reinterpret_cast<const float4*>(&sB[0][kk][tx*4]);
                float4 bi4 = *reinterpret_cast<const float4*>(&sB[1][kk][tx*4]);
                float arr[4]={ar4.x,ar4.y,ar4.z,ar4.w};
                float aii[4]={ai4.x,ai4.y,ai4.z,ai4.w};
                float brr[4]={br4.x,br4.y,br4.z,br4.w};
                float bii[4]={bi4.x,bi4.y,bi4.z,bi4.w};
                #pragma unroll
                for (int i=0;i<4;i++){
                    #pragma unroll
                    for (int j=0;j<4;j++){
                        aRe[i][j] += arr[i]*brr[j] - aii[i]*bii[j];
                        aIm[i][j] += arr[i]*bii[j] + aii[i]*brr[j];
                    }
                }
            }
        } else {
            #pragma unroll 8
            for (int kk=0;kk<32;kk++){
                float4 ar4 = *reinterpret_cast<const float4*>(&sA[0][kk][ty*4]);
                float4 br4 = *reinterpret_cast<const float4*>(&sB[0][kk][tx*4]);
                float arr[4]={ar4.x,ar4.y,ar4.z,ar4.w};
                float brr[4]={br4.x,br4.y,br4.z,br4.w};
                #pragma unroll
                for (int i=0;i<4;i++){
                    #pragma unroll
                    for (int j=0;j<4;j++)
                        aRe[i][j] += arr[i]*brr[j];
                }
            }
        }
    }

    #pragma unroll
    for (int i=0;i<4;i++){
        int n = nBase + ty*4 + i;
        if (n < Nn){
            float4* p0 = reinterpret_cast<float4*>(O0 + (size_t)n*stride + jBase + tx*4);
            *p0 = make_float4(aRe[i][0],aRe[i][1],aRe[i][2],aRe[i][3]);
            if (dual){
                float4* p1 = reinterpret_cast<float4*>(O1 + (size_t)n*stride + jBase + tx*4);
                *p1 = make_float4(aIm[i][0],aIm[i][1],aIm[i][2],aIm[i][3]);
            }
        }
    }
}

// ---------------------------------------------------------------------------
// Gates: Z, Rg = sigmoid(ifft([AX|AH]@[Wx;Wh]) + b); G = Rg*Hs; store Z, fft(G)
// Supports two sections (layers) via blockIdx.y.
// ---------------------------------------------------------------------------
__global__ void gates2_kernel(
    const float* __restrict__ Hs0, const float* __restrict__ bias0,
    int colBase0, int C0, int wb0, int gcol0, int z0,
    const float* __restrict__ Hs1, const float* __restrict__ bias1,
    int colBase1, int C1, int wb1, int gcol1, int z1)
{
    int n = blockIdx.x;
    int sec = blockIdx.y >> 2;
    int bBase = (blockIdx.y & 3)*8;
    const float* Hs; const float* bias; int colBase,C,wb,gcol,zi;
    if (sec==0){ Hs=Hs0; bias=bias0; colBase=colBase0; C=C0; wb=wb0; gcol=gcol0; zi=z0; }
    else       { Hs=Hs1; bias=bias1; colBase=colBase1; C=C1; wb=wb1; gcol=gcol1; zi=z1; }

    __shared__ float sX[8][4][64];
    int tid = threadIdx.y*32 + threadIdx.x;
    int tot = 8*4*C;
    for (int i=tid;i<tot;i+=256){
        int bl = i/(4*C); int rem = i - bl*4*C; int s = rem / C; int c = rem - s*C;
        sX[bl][s][c] = g_AXH[(size_t)s*Nn*JX + (size_t)n*JX + colBase + (bBase+bl)*C + c];
    }
    __syncthreads();
    int h = threadIdx.x, bl = threadIdx.y, b = bBase + bl;
    const float* Wz = g_W + wb;
    const float* Wr = g_W + wb + 4*2048;
    float yz0=0,yz1r=0,yz1i=0,yz2=0, yr0=0,yr1r=0,yr1i=0,yr2=0;
    for (int c=0;c<C;c++){
        float x0=sX[bl][0][c], x1r=sX[bl][1][c], x1i=sX[bl][2][c], x2=sX[bl][3][c];
        int wo = c*32 + h;
        float w0=Wz[wo], w1=Wz[2048+wo], w2=Wz[2*2048+wo], w3=Wz[3*2048+wo];
        yz0 += x0*w0; yz1r += x1r*w1 - x1i*w2; yz1i += x1r*w2 + x1i*w1; yz2 += x2*w3;
        w0=Wr[wo]; w1=Wr[2048+wo]; w2=Wr[2*2048+wo]; w3=Wr[3*2048+wo];
        yr0 += x0*w0; yr1r += x1r*w1 - x1i*w2; yr1i += x1r*w2 + x1i*w1; yr2 += x2*w3;
    }
    float vz[4] = {0.25f*(yz0+yz2+2.f*yz1r), 0.25f*(yz0-yz2-2.f*yz1i),
                   0.25f*(yz0+yz2-2.f*yz1r), 0.25f*(yz0-yz2+2.f*yz1i)};
    float vr[4] = {0.25f*(yr0+yr2+2.f*yr1r), 0.25f*(yr0-yr2-2.f*yr1i),
                   0.25f*(yr0+yr2-2.f*yr1r), 0.25f*(yr0-yr2+2.f*yr1i)};
    size_t hoff = (((size_t)b*Nn + n)*Hh + h)*4;
    float* Z = g_Z + (size_t)zi*HSZ;
    float g[4];
    #pragma unroll
    for (int r=0;r<4;r++){
        float z  = 1.f/(1.f+expf(-(vz[r] + bias[0*128 + h*4 + r])));
        float rg = 1.f/(1.f+expf(-(vr[r] + bias[1*128 + h*4 + r])));
        float hs = Hs ? Hs[hoff + r] : 0.f;
        g[r] = rg*hs;
        Z[hoff + r] = z;
    }
    size_t gb = (size_t)n*JG + gcol + b*Hh + h;
    g_Gf[0*(size_t)NP*JG + gb] = g[0]+g[1]+g[2]+g[3];
    g_Gf[1*(size_t)NP*JG + gb] = g[0]-g[2];
    g_Gf[2*(size_t)NP*JG + gb] = g[3]-g[1];
    g_Gf[3*(size_t)NP*JG + gb] = g[0]-g[1]+g[2]-g[3];
}

// ---------------------------------------------------------------------------
// Ht = tanh(ifft([AX|AG]@[Wxh;Whr]) + bh); Hnew = Z*Hs + (1-Z)*Ht. Two sections.
// ---------------------------------------------------------------------------
__global__ void ht2_kernel(int t,
    const float* __restrict__ Hs0, const float* __restrict__ bias0,
    int colBase0, int C0, int Fin0, int gcol0, int wb0, int z0,
    float* __restrict__ Hnew0, float* __restrict__ out0, float* __restrict__ tail0,
    const float* __restrict__ Hs1, const float* __restrict__ bias1,
    int colBase1, int C1, int Fin1, int gcol1, int wb1, int z1,
    float* __restrict__ Hnew1, float* __restrict__ out1, float* __restrict__ tail1)
{
    int n = blockIdx.x;
    int sec = blockIdx.y >> 2;
    int bBase = (blockIdx.y & 3)*8;
    const float* Hs; const float* bias; int colBase,C,Fin,gcol,wb,zi;
    float *Hnew, *outp, *tailp;
    if (sec==0){ Hs=Hs0; bias=bias0; colBase=colBase0; C=C0; Fin=Fin0; gcol=gcol0; wb=wb0; zi=z0;
                 Hnew=Hnew0; outp=out0; tailp=tail0; }
    else       { Hs=Hs1; bias=bias1; colBase=colBase1; C=C1; Fin=Fin1; gcol=gcol1; wb=wb1; zi=z1;
                 Hnew=Hnew1; outp=out1; tailp=tail1; }

    __shared__ float sXx[8][4][32];
    __shared__ float sG[8][4][32];
    int tid = threadIdx.y*32 + threadIdx.x;
    int tot1 = 8*4*Fin;
    for (int i=tid;i<tot1;i+=256){
        int bl=i/(4*Fin); int rem=i-bl*4*Fin; int s=rem/Fin; int c=rem-s*Fin;
        sXx[bl][s][c] = g_AXH[(size_t)s*Nn*JX + (size_t)n*JX + colBase + (bBase+bl)*C + c];
    }
    for (int i=tid;i<8*4*32;i+=256){
        int bl=i>>7; int rem=i&127; int s=rem>>5; int c=rem&31;
        sG[bl][s][c] = g_AG[(size_t)s*Nn*JG + (size_t)n*JG + gcol + (bBase+bl)*Hh + c];
    }
    __syncthreads();
    int h=threadIdx.x, bl=threadIdx.y, b=bBase+bl;
    const float* Wh = g_W + wb;
    float y0=0,y1r=0,y1i=0,y2=0;
    for (int c=0;c<Fin;c++){
        float x0=sXx[bl][0][c],x1r=sXx[bl][1][c],x1i=sXx[bl][2][c],x2=sXx[bl][3][c];
        int wo=c*32+h;
        float w0=Wh[wo],w1=Wh[2048+wo],w2=Wh[2*2048+wo],w3=Wh[3*2048+wo];
        y0+=x0*w0; y1r+=x1r*w1-x1i*w2; y1i+=x1r*w2+x1i*w1; y2+=x2*w3;
    }
    for (int c=0;c<Hh;c++){
        float x0=sG[bl][0][c],x1r=sG[bl][1][c],x1i=sG[bl][2][c],x2=sG[bl][3][c];
        int wo=(Fin+c)*32+h;
        float w0=Wh[wo],w1=Wh[2048+wo],w2=Wh[2*2048+wo],w3=Wh[3*2048+wo];
        y0+=x0*w0; y1r+=x1r*w1-x1i*w2; y1i+=x1r*w2+x1i*w1; y2+=x2*w3;
    }
    float v[4] = {0.25f*(y0+y2+2.f*y1r), 0.25f*(y0-y2-2.f*y1i),
                  0.25f*(y0+y2-2.f*y1r), 0.25f*(y0-y2+2.f*y1i)};
    size_t hoff = (((size_t)b*Nn+n)*Hh + h)*4;
    const float* Z = g_Z + (size_t)zi*HSZ;
    #pragma unroll
    for (int r=0;r<4;r++){
        float ht = tanhf(v[r] + bias[2*128 + h*4 + r]);
        float z  = Z[hoff+r];
        float hs = Hs ? Hs[hoff+r] : 0.f;
        float hn = z*hs + (1.f-z)*ht;
        Hnew[hoff+r] = hn;
        if (outp)  outp[(((size_t)b*Tt + t)*Nn + n)*(Hh*4) + h*4 + r] = hn;
        if (tailp) tailp[hoff+r] = hn;
    }
}

// ---------------------------------------------------------------------------
// Host orchestration
// ---------------------------------------------------------------------------
extern "C" void kernel_launch(void* const* d_in, const int* in_sizes, int n_in,
                              void* d_out, int out_size) {
    (void)in_sizes; (void)n_in;
    const float* inputs = (const float*)d_in[0];
    const float* U      = (const float*)d_in[1];
    const float* B0p    = (const float*)d_in[7];
    const float* B1p    = (const float*)d_in[13];
    float* out = (float*)d_out;
    const int OUTSZ = Bb*Tt*Nn*Hh*Rr;
    float* tail = (out_size >= OUTSZ + 2*HSZ) ? (out + OUTSZ) : nullptr;

    void* p;
    cudaGetSymbolAddress(&p, g_At);  float* Atp  = (float*)p;
    cudaGetSymbolAddress(&p, g_XHf); float* XHf  = (float*)p;
    cudaGetSymbolAddress(&p, g_Gf);  float* Gfp  = (float*)p;
    cudaGetSymbolAddress(&p, g_AXH); float* AXH  = (float*)p;
    cudaGetSymbolAddress(&p, g_AG);  float* AG   = (float*)p;
    cudaGetSymbolAddress(&p, g_H);   float* Hb   = (float*)p;
    float* H0[2] = {Hb,          Hb +   HSZ};
    float* H1[2] = {Hb + 2*HSZ,  Hb + 3*HSZ};

    // zero the padded buffers (rows 150..159 must read as 0 in the GEMMs)
    cudaMemsetAsync(Atp, 0, sizeof(float)*4*NP*NR);
    cudaMemsetAsync(XHf, 0, sizeof(float)*4*NP*JX);
    cudaMemsetAsync(Gfp, 0, sizeof(float)*4*NP*JG);

    adj_kernel<<<Nn, 256>>>(U);
    wprep_kernel<<<48, 256>>>((const float*)d_in[2], (const float*)d_in[3], (const float*)d_in[4],
                              (const float*)d_in[5], (const float*)d_in[6],
                              (const float*)d_in[8], (const float*)d_in[9], (const float*)d_in[10],
                              (const float*)d_in[11], (const float*)d_in[12]);

    const int WB_Z0 = 0;           // (0*3+0)*4*2048
    const int WB_H0 = 2*4*2048;    // (0*3+2)
    const int WB_Z1 = 3*4*2048;    // (1*3+0)
    const int WB_H1 = 5*4*2048;    // (1*3+2)

    // ---- t = 0, layer0 (single section) ----
    {
        int J = Bb*48;  // 1536
        fft2_kernel<<<(Nn*J+255)/256, 256>>>(J, inputs, Tt*Nn*Ff*Rr, Ff*Rr, nullptr, 48,
                                             nullptr, 0, 0, nullptr, 64, J);
        agg2_kernel<<<dim3(J/64,3,3), dim3(16,16)>>>(XHf, AXH, JX);
        gates2_kernel<<<dim3(Nn,4), dim3(32,8)>>>(nullptr, B0p, 0, 48, WB_Z0, 0, 0,
                                                  nullptr, B0p, 0, 48, WB_Z0, 0, 0);
        agg2_kernel<<<dim3(1024/64,3,3), dim3(16,16)>>>(Gfp, AG, JG);
        ht2_kernel<<<dim3(Nn,4), dim3(32,8)>>>(0,
            nullptr, B0p, 0, 48, 16, 0, WB_H0, 0, H0[0], nullptr, nullptr,
            nullptr, B0p, 0, 48, 16, 0, WB_H0, 0, H0[0], nullptr, nullptr);
    }
    // ---- t = 0, layer1 consumes CURRENT layer0 output ----
    {
        int J = Bb*64;  // 2048
        fft2_kernel<<<(Nn*J+255)/256, 256>>>(J, H0[0], Nn*Hh*Rr, Hh*Rr, nullptr, 64,
                                             nullptr, 0, 0, nullptr, 64, J);
        agg2_kernel<<<dim3(J/64,3,3), dim3(16,16)>>>(XHf, AXH, JX);
        gates2_kernel<<<dim3(Nn,4), dim3(32,8)>>>(nullptr, B1p, 0, 64, WB_Z1, 0, 1,
                                                  nullptr, B1p, 0, 64, WB_Z1, 0, 1);
        agg2_kernel<<<dim3(1024/64,3,3), dim3(16,16)>>>(Gfp, AG, JG);
        ht2_kernel<<<dim3(Nn,4), dim3(32,8)>>>(0,
            nullptr, B1p, 0, 64, 32, 0, WB_H1, 1, H1[0], out, nullptr,
            nullptr, B1p, 0, 64, 32, 0, WB_H1, 1, H1[0], out, nullptr);
    }

    // ---- t = 1..7: layer0(t) and layer1(t) are independent -> combined ----
    int c0 = 0, c1 = 0;
    for (int t=1; t<Tt; t++){
        float* tl0 = (t==Tt-1 && tail) ? tail        : nullptr;
        float* tl1 = (t==Tt-1 && tail) ? tail + HSZ  : nullptr;
        const float* Xt = inputs + (size_t)t*Nn*Ff*Rr;
        int J = 1536 + 2048;  // 3584

        fft2_kernel<<<(Nn*J+255)/256, 256>>>(J,
            Xt, Tt*Nn*Ff*Rr, Ff*Rr, H0[c0], 48,
            H0[c0], Nn*Hh*Rr, Hh*Rr, H1[c1], 64, 1536);
        agg2_kernel<<<dim3(J/64,3,3), dim3(16,16)>>>(XHf, AXH, JX);
        gates2_kernel<<<dim3(Nn,8), dim3(32,8)>>>(
            H0[c0], B0p, 0,    48, WB_Z0, 0,    0,
            H1[c1], B1p, 1536, 64, WB_Z1, 1024, 1);
        agg2_kernel<<<dim3(2048/64,3,3), dim3(16,16)>>>(Gfp, AG, JG);
        ht2_kernel<<<dim3(Nn,8), dim3(32,8)>>>(t,
            H0[c0], B0p, 0,    48, 16, 0,    WB_H0, 0, H0[c0^1], nullptr, tl0,
            H1[c1], B1p, 1536, 64, 32, 1024, WB_H1, 1, H1[c1^1], out,     tl1);
        c0 ^= 1; c1 ^= 1;
    }
}

// round 3
// speedup vs baseline: 1.4419x; 1.2162x over previous
#include <cuda_runtime.h>
#include <math.h>

#define Bb 32
#define Tt 8
#define Nn 150
#define Ff 16
#define Hh 32
#define Rr 4
#define Ee 16

#define NP 160                 // K dim padded
#define NR 192                 // row dim padded (3 x 64 tiles)
#define JX 3584                // col stride for XHf / AXH
#define JG 2048                // col stride for Gf / AG
#define HSZ (Bb*Nn*Hh*Rr)

// slots: 0=f0, 1=X1(Re f1), 2=X2(Im f1), 3=f2, 4=X1+X2 (Karatsuba)
__device__ float g_At[5*NP*NR];
__device__ float g_W[2*3*4*64*32];
__device__ float g_XHf[5*NP*JX];
__device__ float g_AXH[5*Nn*JX];
__device__ float g_Gf[5*NP*JG];
__device__ float g_AG[5*Nn*JG];
__device__ float g_Z[2*HSZ];
__device__ float g_H[4*HSZ];

// ---------------------------------------------------------------------------
__global__ void adj_kernel(const float* __restrict__ U) {
    __shared__ float sUf[Ee][4];
    __shared__ float red[256];
    int n = blockIdx.x;
    int tid = threadIdx.x;
    if (tid < Ee*4) {
        int e = tid >> 2, s = tid & 3;
        const float* p = U + (n*Ee + e)*4;
        float u0=p[0],u1=p[1],u2=p[2],u3=p[3];
        float v;
        if (s==0) v = u0+u1+u2+u3;
        else if (s==1) v = u0-u2;
        else if (s==2) v = u3-u1;
        else v = u0-u1+u2-u3;
        sUf[e][s] = v;
    }
    __syncthreads();
    int m = tid;
    float a0=0.f,a1=0.f,a2=0.f,a3=0.f;
    if (m < Nn) {
        float P0=0.f,P1r=0.f,P1i=0.f,P2=0.f;
        #pragma unroll
        for (int e=0;e<Ee;e++){
            const float* p = U + (m*Ee + e)*4;
            float u0=p[0],u1=p[1],u2=p[2],u3=p[3];
            float m0=u0+u1+u2+u3, m1r=u0-u2, m1i=u3-u1, m2=u0-u1+u2-u3;
            float q0=sUf[e][0], q1r=sUf[e][1], q1i=sUf[e][2], q2=sUf[e][3];
            P0  += q0*m0;
            P2  += q2*m2;
            P1r += q1r*m1r - q1i*m1i;
            P1i += q1r*m1i + q1i*m1r;
        }
        a0 = fmaxf(0.25f*(P0 + P2 + 2.f*P1r), 0.f);
        a1 = fmaxf(0.25f*(P0 - P2 - 2.f*P1i), 0.f);
        a2 = fmaxf(0.25f*(P0 + P2 - 2.f*P1r), 0.f);
        a3 = fmaxf(0.25f*(P0 - P2 + 2.f*P1i), 0.f);
    }
    float av[4] = {a0,a1,a2,a3};
    float v[4];
    for (int r=0;r<4;r++){
        red[tid] = (m<Nn) ? av[r] : -1e30f; __syncthreads();
        for (int s=128;s>0;s>>=1){ if (tid<s) red[tid]=fmaxf(red[tid],red[tid+s]); __syncthreads(); }
        float mx = red[0]; __syncthreads();
        float ex = (m<Nn) ? expf(av[r]-mx) : 0.f;
        red[tid] = ex; __syncthreads();
        for (int s=128;s>0;s>>=1){ if (tid<s) red[tid]+=red[tid+s]; __syncthreads(); }
        float sm = red[0]; __syncthreads();
        v[r] = ex / sm;
    }
    if (m < Nn) {
        float s1 = v[0]-v[2];
        float s2 = v[3]-v[1];
        g_At[0*NP*NR + m*NR + n] = v[0]+v[1]+v[2]+v[3];
        g_At[1*NP*NR + m*NR + n] = s1;
        g_At[2*NP*NR + m*NR + n] = s2;
        g_At[3*NP*NR + m*NR + n] = v[0]-v[1]+v[2]-v[3];
        g_At[4*NP*NR + m*NR + n] = s1 + s2;
    }
}

// ---------------------------------------------------------------------------
__global__ void wprep_kernel(const float* wxz0,const float* wxr0,const float* wxh0,
                             const float* whz0,const float* whr0,
                             const float* wxz1,const float* wxr1,const float* wxh1,
                             const float* whz1,const float* whr1) {
    int idx = blockIdx.x*blockDim.x + threadIdx.x;
    if (idx >= 2*3*64*32) return;
    int h = idx & 31;
    int c = (idx >> 5) & 63;
    int g = (idx >> 11) % 3;
    int l = idx / (3*64*32);
    int Fin = l ? 32 : 16;
    int C = Fin + 32;
    float w[4] = {0.f,0.f,0.f,0.f};
    if (c < C) {
        bool xp = c < Fin;
        int row = xp ? c : (c - Fin);
        const float* src;
        if (l == 0)
            src = (g==0) ? (xp? wxz0: whz0) : (g==1) ? (xp? wxr0: whr0) : (xp? wxh0: whr0);
        else
            src = (g==0) ? (xp? wxz1: whz1) : (g==1) ? (xp? wxr1: whr1) : (xp? wxh1: whr1);
        const float* p = src + (row*Hh + h)*4;
        float u0=p[0],u1=p[1],u2=p[2],u3=p[3];
        w[0]=u0+u1+u2+u3; w[1]=u0-u2; w[2]=u3-u1; w[3]=u0-u1+u2-u3;
    }
    int base = ((l*3+g)*4)*2048 + c*32 + h;
    #pragma unroll
    for (int s=0;s<4;s++) g_W[base + s*2048] = w[s];
}

// ---------------------------------------------------------------------------
// fft of up to two column sections -> g_XHf (5 slots)
// ---------------------------------------------------------------------------
__global__ void fft2_kernel(int J,
    const float* __restrict__ x0, int xb0, int xn0, const float* __restrict__ h0, int C0,
    const float* __restrict__ x1, int xb1, int xn1, const float* __restrict__ h1, int C1,
    int colBase1)
{
    int total = Nn*J;
    const size_t SS = (size_t)NP*JX;
    for (int idx = blockIdx.x*blockDim.x+threadIdx.x; idx < total; idx += gridDim.x*blockDim.x){
        int n = idx / J, col = idx - n*J;
        const float* xp; const float* hp; int xb,xn,C,q;
        if (col < colBase1){ q = col; C = C0; xp=x0; xb=xb0; xn=xn0; hp=h0; }
        else               { q = col-colBase1; C=C1; xp=x1; xb=xb1; xn=xn1; hp=h1; }
        int Fin = C - 32;
        int b = q / C, c = q - b*C;
        float v0,v1,v2,v3;
        if (c < Fin){
            const float4 vv = *reinterpret_cast<const float4*>(xp + (size_t)b*xb + (size_t)n*xn + c*4);
            v0=vv.x; v1=vv.y; v2=vv.z; v3=vv.w;
        } else if (hp){
            const float4 vv = *reinterpret_cast<const float4*>(hp + (((size_t)b*Nn+n)*Hh + (c-Fin))*4);
            v0=vv.x; v1=vv.y; v2=vv.z; v3=vv.w;
        } else { v0=v1=v2=v3=0.f; }
        size_t base = (size_t)n*JX + col;
        float s1 = v0-v2, s2 = v3-v1;
        g_XHf[0*SS + base] = v0+v1+v2+v3;
        g_XHf[1*SS + base] = s1;
        g_XHf[2*SS + base] = s2;
        g_XHf[3*SS + base] = v0-v1+v2-v3;
        g_XHf[4*SS + base] = s1 + s2;
    }
}

// ---------------------------------------------------------------------------
// Aggregation GEMM: Out[s] = A[s] @ X[s], 5 identical real slots.
// Tile 64(rows) x 128(cols), threads (32,8), 8x4 per thread, double-buffered.
// ---------------------------------------------------------------------------
__global__ __launch_bounds__(256) void agg3_kernel(const float* __restrict__ Xf,
                                                   float* __restrict__ Out, int stride){
    int s = blockIdx.z;
    const float* A = g_At + (size_t)s*NP*NR;
    const float* X = Xf + (size_t)s*NP*stride;
    float* O = Out + (size_t)s*Nn*stride;
    int nBase = blockIdx.y*64, jBase = blockIdx.x*128;

    __shared__ float sA[2][16][64];
    __shared__ float sB[2][16][128];
    int tx=threadIdx.x, ty=threadIdx.y, tid=ty*32+tx;

    int ak = tid>>4, an = (tid&15)*4;
    int bk = tid>>5, bc = (tid&31)*4;
    const float* Ap = A + (size_t)ak*NR + nBase + an;
    const float* Bp = X + (size_t)bk*stride + jBase + bc;

    float4 ra, rb0, rb1;
    ra  = *reinterpret_cast<const float4*>(Ap);
    rb0 = *reinterpret_cast<const float4*>(Bp);
    rb1 = *reinterpret_cast<const float4*>(Bp + 8*(size_t)stride);
    *reinterpret_cast<float4*>(&sA[0][ak][an]) = ra;
    *reinterpret_cast<float4*>(&sB[0][bk][bc]) = rb0;
    *reinterpret_cast<float4*>(&sB[0][8+bk][bc]) = rb1;
    __syncthreads();

    float acc[2][4][4] = {};
    for (int ch=0; ch<10; ch++){
        int buf = ch&1;
        if (ch<9){
            size_t ko = (size_t)(ch+1)*16;
            ra  = *reinterpret_cast<const float4*>(Ap + ko*NR);
            rb0 = *reinterpret_cast<const float4*>(Bp + ko*stride);
            rb1 = *reinterpret_cast<const float4*>(Bp + (ko+8)*stride);
        }
        #pragma unroll
        for (int kk=0;kk<16;kk++){
            float4 a0 = *reinterpret_cast<const float4*>(&sA[buf][kk][ty*4]);
            float4 a1 = *reinterpret_cast<const float4*>(&sA[buf][kk][32+ty*4]);
            float4 b  = *reinterpret_cast<const float4*>(&sB[buf][kk][tx*4]);
            float aa0[4]={a0.x,a0.y,a0.z,a0.w};
            float aa1[4]={a1.x,a1.y,a1.z,a1.w};
            float bv[4]={b.x,b.y,b.z,b.w};
            #pragma unroll
            for (int i=0;i<4;i++){
                #pragma unroll
                for (int j=0;j<4;j++){
                    acc[0][i][j] += aa0[i]*bv[j];
                    acc[1][i][j] += aa1[i]*bv[j];
                }
            }
        }
        if (ch<9){
            int nb = buf^1;
            *reinterpret_cast<float4*>(&sA[nb][ak][an]) = ra;
            *reinterpret_cast<float4*>(&sB[nb][bk][bc]) = rb0;
            *reinterpret_cast<float4*>(&sB[nb][8+bk][bc]) = rb1;
        }
        __syncthreads();
    }
    #pragma unroll
    for (int ri=0; ri<2; ri++){
        #pragma unroll
        for (int i=0;i<4;i++){
            int n = nBase + ri*32 + ty*4 + i;
            if (n < Nn)
                *reinterpret_cast<float4*>(O + (size_t)n*stride + jBase + tx*4) =
                    make_float4(acc[ri][i][0],acc[ri][i][1],acc[ri][i][2],acc[ri][i][3]);
        }
    }
}

// ---------------------------------------------------------------------------
// Gates. block (32,4)=128 thr; thread = (h, bt), handles 8 batches.
// ---------------------------------------------------------------------------
__global__ void gates3_kernel(
    const float* __restrict__ Hs0, const float* __restrict__ bias0,
    int colBase0, int C0, int wb0, int gcol0, int z0,
    const float* __restrict__ Hs1, const float* __restrict__ bias1,
    int colBase1, int C1, int wb1, int gcol1, int z1)
{
    int n = blockIdx.x;
    int sec = blockIdx.y;
    const float* Hs; const float* bias; int colBase,C,wb,gcol,zi;
    if (sec==0){ Hs=Hs0; bias=bias0; colBase=colBase0; C=C0; wb=wb0; gcol=gcol0; zi=z0; }
    else       { Hs=Hs1; bias=bias1; colBase=colBase1; C=C1; wb=wb1; gcol=gcol1; zi=z1; }

    __shared__ float sX[4][64][33];
    int tid = threadIdx.y*32 + threadIdx.x;
    const float* AX = g_AXH;
    const size_t SS = (size_t)Nn*JX;
    size_t rowb = (size_t)n*JX + colBase;
    int tot = 4*C*32;
    for (int i=tid;i<tot;i+=128){
        int c = i % C; int sb = i / C; int s = sb >> 5; int b = sb & 31;
        size_t base = rowb + b*C + c;
        float v;
        if (s==0)      v = AX[base];
        else if (s==1) v = AX[SS+base] - AX[2*SS+base];
        else if (s==2) v = AX[4*SS+base] - AX[SS+base] - AX[2*SS+base];
        else           v = AX[3*SS+base];
        sX[s][c][b] = v;
    }
    __syncthreads();

    int h = threadIdx.x, bt = threadIdx.y;
    const float* Wz = g_W + wb;
    const float* Wr = Wz + 4*2048;
    float yz0[8]={},yz1[8]={},yz2[8]={},yz3[8]={};
    float yr0[8]={},yr1[8]={},yr2[8]={},yr3[8]={};
    for (int c=0;c<C;c++){
        int wo = c*32 + h;
        float wz0=Wz[wo],wz1=Wz[2048+wo],wz2=Wz[4096+wo],wz3=Wz[6144+wo];
        float wr0=Wr[wo],wr1=Wr[2048+wo],wr2=Wr[4096+wo],wr3=Wr[6144+wo];
        #pragma unroll
        for (int bb=0;bb<8;bb++){
            int b = bt*8+bb;
            float x0=sX[0][c][b], x1r=sX[1][c][b], x1i=sX[2][c][b], x2=sX[3][c][b];
            yz0[bb] += x0*wz0;
            yz1[bb] += x1r*wz1 - x1i*wz2;
            yz2[bb] += x1r*wz2 + x1i*wz1;
            yz3[bb] += x2*wz3;
            yr0[bb] += x0*wr0;
            yr1[bb] += x1r*wr1 - x1i*wr2;
            yr2[bb] += x1r*wr2 + x1i*wr1;
            yr3[bb] += x2*wr3;
        }
    }
    float bz[4], br[4];
    #pragma unroll
    for (int r=0;r<4;r++){ bz[r]=bias[h*4+r]; br[r]=bias[128+h*4+r]; }
    float* Z = g_Z + (size_t)zi*HSZ;
    const size_t GS = (size_t)NP*JG;
    #pragma unroll
    for (int bb=0;bb<8;bb++){
        int b = bt*8+bb;
        float vz[4] = {0.25f*(yz0[bb]+yz3[bb]+2.f*yz1[bb]), 0.25f*(yz0[bb]-yz3[bb]-2.f*yz2[bb]),
                       0.25f*(yz0[bb]+yz3[bb]-2.f*yz1[bb]), 0.25f*(yz0[bb]-yz3[bb]+2.f*yz2[bb])};
        float vr[4] = {0.25f*(yr0[bb]+yr3[bb]+2.f*yr1[bb]), 0.25f*(yr0[bb]-yr3[bb]-2.f*yr2[bb]),
                       0.25f*(yr0[bb]+yr3[bb]-2.f*yr1[bb]), 0.25f*(yr0[bb]-yr3[bb]+2.f*yr2[bb])};
        size_t hoff = (((size_t)b*Nn + n)*Hh + h)*4;
        float4 hs4 = Hs ? *reinterpret_cast<const float4*>(Hs + hoff) : make_float4(0,0,0,0);
        float hsv[4] = {hs4.x,hs4.y,hs4.z,hs4.w};
        float g[4], zv[4];
        #pragma unroll
        for (int r=0;r<4;r++){
            zv[r] = 1.f/(1.f+expf(-(vz[r] + bz[r])));
            float rg = 1.f/(1.f+expf(-(vr[r] + br[r])));
            g[r] = rg*hsv[r];
        }
        *reinterpret_cast<float4*>(Z + hoff) = make_float4(zv[0],zv[1],zv[2],zv[3]);
        size_t gb = (size_t)n*JG + gcol + b*Hh + h;
        float s1 = g[0]-g[2], s2 = g[3]-g[1];
        g_Gf[0*GS + gb] = g[0]+g[1]+g[2]+g[3];
        g_Gf[1*GS + gb] = s1;
        g_Gf[2*GS + gb] = s2;
        g_Gf[3*GS + gb] = g[0]-g[1]+g[2]-g[3];
        g_Gf[4*GS + gb] = s1 + s2;
    }
}

// ---------------------------------------------------------------------------
// Ht + hidden update. block (32,4); thread handles 8 batches. gcol<0 -> no G term.
// ---------------------------------------------------------------------------
__global__ void ht3_kernel(int t,
    const float* __restrict__ Hs0, const float* __restrict__ bias0,
    int colBase0, int C0, int Fin0, int gcol0, int wb0, int z0,
    float* __restrict__ Hnew0, float* __restrict__ out0, float* __restrict__ tail0,
    const float* __restrict__ Hs1, const float* __restrict__ bias1,
    int colBase1, int C1, int Fin1, int gcol1, int wb1, int z1,
    float* __restrict__ Hnew1, float* __restrict__ out1, float* __restrict__ tail1)
{
    int n = blockIdx.x;
    int sec = blockIdx.y;
    const float* Hs; const float* bias; int colBase,C,Fin,gcol,wb,zi;
    float *Hnew, *outp, *tailp;
    if (sec==0){ Hs=Hs0; bias=bias0; colBase=colBase0; C=C0; Fin=Fin0; gcol=gcol0; wb=wb0; zi=z0;
                 Hnew=Hnew0; outp=out0; tailp=tail0; }
    else       { Hs=Hs1; bias=bias1; colBase=colBase1; C=C1; Fin=Fin1; gcol=gcol1; wb=wb1; zi=z1;
                 Hnew=Hnew1; outp=out1; tailp=tail1; }
    bool useG = (gcol >= 0);

    __shared__ float sXx[4][32][33];
    __shared__ float sG[4][32][33];
    int tid = threadIdx.y*32 + threadIdx.x;
    const size_t SS = (size_t)Nn*JX;
    const size_t AS = (size_t)Nn*JG;
    size_t rowb = (size_t)n*JX + colBase;
    int tot = 4*Fin*32;
    for (int i=tid;i<tot;i+=128){
        int c = i % Fin; int sb = i / Fin; int s = sb >> 5; int b = sb & 31;
        size_t base = rowb + b*C + c;
        const float* AX = g_AXH;
        float v;
        if (s==0)      v = AX[base];
        else if (s==1) v = AX[SS+base] - AX[2*SS+base];
        else if (s==2) v = AX[4*SS+base] - AX[SS+base] - AX[2*SS+base];
        else           v = AX[3*SS+base];
        sXx[s][c][b] = v;
    }
    if (useG){
        size_t growb = (size_t)n*JG + gcol;
        for (int i=tid;i<4*32*32;i+=128){
            int c = i & 31; int sb = i >> 5; int s = sb >> 5; int b = sb & 31;
            size_t base = growb + b*Hh + c;
            const float* AG = g_AG;
            float v;
            if (s==0)      v = AG[base];
            else if (s==1) v = AG[AS+base] - AG[2*AS+base];
            else if (s==2) v = AG[4*AS+base] - AG[AS+base] - AG[2*AS+base];
            else           v = AG[3*AS+base];
            sG[s][c][b] = v;
        }
    }
    __syncthreads();

    int h = threadIdx.x, bt = threadIdx.y;
    const float* Wh = g_W + wb;
    float y0[8]={},y1[8]={},y2[8]={},y3[8]={};
    for (int c=0;c<Fin;c++){
        int wo = c*32 + h;
        float w0=Wh[wo],w1=Wh[2048+wo],w2=Wh[4096+wo],w3=Wh[6144+wo];
        #pragma unroll
        for (int bb=0;bb<8;bb++){
            int b = bt*8+bb;
            float x0=sXx[0][c][b], x1r=sXx[1][c][b], x1i=sXx[2][c][b], x2=sXx[3][c][b];
            y0[bb] += x0*w0;
            y1[bb] += x1r*w1 - x1i*w2;
            y2[bb] += x1r*w2 + x1i*w1;
            y3[bb] += x2*w3;
        }
    }
    if (useG){
        for (int c=0;c<Hh;c++){
            int wo = (Fin+c)*32 + h;
            float w0=Wh[wo],w1=Wh[2048+wo],w2=Wh[4096+wo],w3=Wh[6144+wo];
            #pragma unroll
            for (int bb=0;bb<8;bb++){
                int b = bt*8+bb;
                float x0=sG[0][c][b], x1r=sG[1][c][b], x1i=sG[2][c][b], x2=sG[3][c][b];
                y0[bb] += x0*w0;
                y1[bb] += x1r*w1 - x1i*w2;
                y2[bb] += x1r*w2 + x1i*w1;
                y3[bb] += x2*w3;
            }
        }
    }
    float bh[4];
    #pragma unroll
    for (int r=0;r<4;r++) bh[r] = bias[256 + h*4 + r];
    const float* Z = g_Z + (size_t)zi*HSZ;
    #pragma unroll
    for (int bb=0;bb<8;bb++){
        int b = bt*8+bb;
        float v[4] = {0.25f*(y0[bb]+y3[bb]+2.f*y1[bb]), 0.25f*(y0[bb]-y3[bb]-2.f*y2[bb]),
                      0.25f*(y0[bb]+y3[bb]-2.f*y1[bb]), 0.25f*(y0[bb]-y3[bb]+2.f*y2[bb])};
        size_t hoff = (((size_t)b*Nn+n)*Hh + h)*4;
        float4 z4 = *reinterpret_cast<const float4*>(Z + hoff);
        float zv[4] = {z4.x,z4.y,z4.z,z4.w};
        float4 hs4 = Hs ? *reinterpret_cast<const float4*>(Hs + hoff) : make_float4(0,0,0,0);
        float hsv[4] = {hs4.x,hs4.y,hs4.z,hs4.w};
        float hn[4];
        #pragma unroll
        for (int r=0;r<4;r++){
            float ht = tanhf(v[r] + bh[r]);
            hn[r] = zv[r]*hsv[r] + (1.f-zv[r])*ht;
        }
        float4 hv = make_float4(hn[0],hn[1],hn[2],hn[3]);
        *reinterpret_cast<float4*>(Hnew + hoff) = hv;
        if (outp)
            *reinterpret_cast<float4*>(outp + (((size_t)b*Tt + t)*Nn + n)*(Hh*4) + h*4) = hv;
        if (tailp)
            *reinterpret_cast<float4*>(tailp + hoff) = hv;
    }
}

// ---------------------------------------------------------------------------
extern "C" void kernel_launch(void* const* d_in, const int* in_sizes, int n_in,
                              void* d_out, int out_size) {
    (void)in_sizes; (void)n_in;
    const float* inputs = (const float*)d_in[0];
    const float* U      = (const float*)d_in[1];
    const float* B0p    = (const float*)d_in[7];
    const float* B1p    = (const float*)d_in[13];
    float* out = (float*)d_out;
    const int OUTSZ = Bb*Tt*Nn*Hh*Rr;
    float* tail = (out_size >= OUTSZ + 2*HSZ) ? (out + OUTSZ) : nullptr;

    void* p;
    cudaGetSymbolAddress(&p, g_At);  float* Atp  = (float*)p;
    cudaGetSymbolAddress(&p, g_XHf); float* XHf  = (float*)p;
    cudaGetSymbolAddress(&p, g_Gf);  float* Gfp  = (float*)p;
    cudaGetSymbolAddress(&p, g_AXH); float* AXH  = (float*)p;
    cudaGetSymbolAddress(&p, g_AG);  float* AG   = (float*)p;
    cudaGetSymbolAddress(&p, g_H);   float* Hb   = (float*)p;
    float* H0[2] = {Hb,          Hb +   HSZ};
    float* H1[2] = {Hb + 2*HSZ,  Hb + 3*HSZ};

    cudaMemsetAsync(Atp, 0, sizeof(float)*5*NP*NR);
    cudaMemsetAsync(XHf, 0, sizeof(float)*5*NP*JX);
    cudaMemsetAsync(Gfp, 0, sizeof(float)*5*NP*JG);

    adj_kernel<<<Nn, 256>>>(U);
    wprep_kernel<<<48, 256>>>((const float*)d_in[2], (const float*)d_in[3], (const float*)d_in[4],
                              (const float*)d_in[5], (const float*)d_in[6],
                              (const float*)d_in[8], (const float*)d_in[9], (const float*)d_in[10],
                              (const float*)d_in[11], (const float*)d_in[12]);

    const int WB_Z0 = 0;
    const int WB_H0 = 2*4*2048;
    const int WB_Z1 = 3*4*2048;
    const int WB_H1 = 5*4*2048;
    dim3 blk128(32,4);

    // ---- t = 0, layer0 ----
    {
        int J = Bb*48;  // 1536
        fft2_kernel<<<(Nn*J+255)/256, 256>>>(J, inputs, Tt*Nn*Ff*Rr, Ff*Rr, nullptr, 48,
                                             nullptr, 0, 0, nullptr, 64, J);
        agg3_kernel<<<dim3(J/128,3,5), dim3(32,8)>>>(XHf, AXH, JX);
        gates3_kernel<<<dim3(Nn,1), blk128>>>(nullptr, B0p, 0, 48, WB_Z0, 0, 0,
                                              nullptr, B0p, 0, 48, WB_Z0, 0, 0);
        ht3_kernel<<<dim3(Nn,1), blk128>>>(0,
            nullptr, B0p, 0, 48, 16, -1, WB_H0, 0, H0[0], nullptr, nullptr,
            nullptr, B0p, 0, 48, 16, -1, WB_H0, 0, H0[0], nullptr, nullptr);
    }
    // ---- t = 0, layer1 ----
    {
        int J = Bb*64;  // 2048
        fft2_kernel<<<(Nn*J+255)/256, 256>>>(J, H0[0], Nn*Hh*Rr, Hh*Rr, nullptr, 64,
                                             nullptr, 0, 0, nullptr, 64, J);
        agg3_kernel<<<dim3(J/128,3,5), dim3(32,8)>>>(XHf, AXH, JX);
        gates3_kernel<<<dim3(Nn,1), blk128>>>(nullptr, B1p, 0, 64, WB_Z1, 0, 1,
                                              nullptr, B1p, 0, 64, WB_Z1, 0, 1);
        ht3_kernel<<<dim3(Nn,1), blk128>>>(0,
            nullptr, B1p, 0, 64, 32, -1, WB_H1, 1, H1[0], out, nullptr,
            nullptr, B1p, 0, 64, 32, -1, WB_H1, 1, H1[0], out, nullptr);
    }

    // ---- t = 1..7: combined layers ----
    int c0 = 0, c1 = 0;
    for (int t=1; t<Tt; t++){
        float* tl0 = (t==Tt-1 && tail) ? tail        : nullptr;
        float* tl1 = (t==Tt-1 && tail) ? tail + HSZ  : nullptr;
        const float* Xt = inputs + (size_t)t*Nn*Ff*Rr;
        int J = 1536 + 2048;  // 3584

        fft2_kernel<<<(Nn*J+255)/256, 256>>>(J,
            Xt, Tt*Nn*Ff*Rr, Ff*Rr, H0[c0], 48,
            H0[c0], Nn*Hh*Rr, Hh*Rr, H1[c1], 64, 1536);
        agg3_kernel<<<dim3(J/128,3,5), dim3(32,8)>>>(XHf, AXH, JX);
        gates3_kernel<<<dim3(Nn,2), blk128>>>(
            H0[c0], B0p, 0,    48, WB_Z0, 0,    0,
            H1[c1], B1p, 1536, 64, WB_Z1, 1024, 1);
        agg3_kernel<<<dim3(JG/128,3,5), dim3(32,8)>>>(Gfp, AG, JG);
        ht3_kernel<<<dim3(Nn,2), blk128>>>(t,
            H0[c0], B0p, 0,    48, 16, 0,    WB_H0, 0, H0[c0^1], nullptr, tl0,
            H1[c1], B1p, 1536, 64, 32, 1024, WB_H1, 1, H1[c1^1], out,     tl1);
        c0 ^= 1; c1 ^= 1;
    }
}

// round 4
// speedup vs baseline: 1.4988x; 1.0395x over previous
#include <cuda_runtime.h>
#include <math.h>

#define Bb 32
#define Tt 8
#define Nn 150
#define Ff 16
#define Hh 32
#define Rr 4
#define Ee 16

#define NP 160                     // padded reduction dim (nodes)
#define NR 192                     // padded row dim (3 x 64 tiles)
#define JB 2560                    // agg1 col space: X(512) | H0(1024) | H1(1024)
#define JG 2048                    // agg2 col space: G0(1024) | G1(1024)
#define XT (NP*512)                // per-t X slot plane
#define HSZ (Bb*Nn*Hh*Rr)

// slots: 0=f0, 1=Re f1, 2=Im f1, 3=f2, 4=slot1+slot2 (Karatsuba)
__device__ float g_At  [5*NP*NR];
__device__ float g_W   [2*3*4*64*32];
__device__ float g_Xall[5*Tt*NP*512];   // fft slots of inputs, all timesteps
__device__ float g_Hf  [5*NP*JG];       // H slot buffer: cols [0,1024)=H0, [1024,2048)=H1
__device__ float g_AXH [5*Nn*JB];       // A @ [X|H0|H1]
__device__ float g_Gf  [5*NP*JG];       // fft slots of Rg*Hs
__device__ float g_AG  [5*Nn*JG];       // A @ Gf
__device__ float g_Z   [2*HSZ];
__device__ float g_H   [4*HSZ];

// ---------------------------------------------------------------------------
__global__ void adj_kernel(const float* __restrict__ U) {
    __shared__ float sUf[Ee][4];
    __shared__ float red[256];
    int n = blockIdx.x;
    int tid = threadIdx.x;
    if (tid < Ee*4) {
        int e = tid >> 2, s = tid & 3;
        const float* p = U + (n*Ee + e)*4;
        float u0=p[0],u1=p[1],u2=p[2],u3=p[3];
        float v;
        if (s==0) v = u0+u1+u2+u3;
        else if (s==1) v = u0-u2;
        else if (s==2) v = u3-u1;
        else v = u0-u1+u2-u3;
        sUf[e][s] = v;
    }
    __syncthreads();
    int m = tid;
    float a0=0.f,a1=0.f,a2=0.f,a3=0.f;
    if (m < Nn) {
        float P0=0.f,P1r=0.f,P1i=0.f,P2=0.f;
        #pragma unroll
        for (int e=0;e<Ee;e++){
            const float* p = U + (m*Ee + e)*4;
            float u0=p[0],u1=p[1],u2=p[2],u3=p[3];
            float m0=u0+u1+u2+u3, m1r=u0-u2, m1i=u3-u1, m2=u0-u1+u2-u3;
            float q0=sUf[e][0], q1r=sUf[e][1], q1i=sUf[e][2], q2=sUf[e][3];
            P0  += q0*m0;
            P2  += q2*m2;
            P1r += q1r*m1r - q1i*m1i;
            P1i += q1r*m1i + q1i*m1r;
        }
        a0 = fmaxf(0.25f*(P0 + P2 + 2.f*P1r), 0.f);
        a1 = fmaxf(0.25f*(P0 - P2 - 2.f*P1i), 0.f);
        a2 = fmaxf(0.25f*(P0 + P2 - 2.f*P1r), 0.f);
        a3 = fmaxf(0.25f*(P0 - P2 + 2.f*P1i), 0.f);
    }
    float av[4] = {a0,a1,a2,a3};
    float v[4];
    for (int r=0;r<4;r++){
        red[tid] = (m<Nn) ? av[r] : -1e30f; __syncthreads();
        for (int s=128;s>0;s>>=1){ if (tid<s) red[tid]=fmaxf(red[tid],red[tid+s]); __syncthreads(); }
        float mx = red[0]; __syncthreads();
        float ex = (m<Nn) ? expf(av[r]-mx) : 0.f;
        red[tid] = ex; __syncthreads();
        for (int s=128;s>0;s>>=1){ if (tid<s) red[tid]+=red[tid+s]; __syncthreads(); }
        float sm = red[0]; __syncthreads();
        v[r] = ex / sm;
    }
    if (m < Nn) {
        float s1 = v[0]-v[2];
        float s2 = v[3]-v[1];
        g_At[0*NP*NR + m*NR + n] = v[0]+v[1]+v[2]+v[3];
        g_At[1*NP*NR + m*NR + n] = s1;
        g_At[2*NP*NR + m*NR + n] = s2;
        g_At[3*NP*NR + m*NR + n] = v[0]-v[1]+v[2]-v[3];
        g_At[4*NP*NR + m*NR + n] = s1 + s2;
    }
}

// ---------------------------------------------------------------------------
__global__ void wprep_kernel(const float* wxz0,const float* wxr0,const float* wxh0,
                             const float* whz0,const float* whr0,
                             const float* wxz1,const float* wxr1,const float* wxh1,
                             const float* whz1,const float* whr1) {
    int idx = blockIdx.x*blockDim.x + threadIdx.x;
    if (idx >= 2*3*64*32) return;
    int h = idx & 31;
    int c = (idx >> 5) & 63;
    int g = (idx >> 11) % 3;
    int l = idx / (3*64*32);
    int Fin = l ? 32 : 16;
    int C = Fin + 32;
    float w[4] = {0.f,0.f,0.f,0.f};
    if (c < C) {
        bool xp = c < Fin;
        int row = xp ? c : (c - Fin);
        const float* src;
        if (l == 0)
            src = (g==0) ? (xp? wxz0: whz0) : (g==1) ? (xp? wxr0: whr0) : (xp? wxh0: whr0);
        else
            src = (g==0) ? (xp? wxz1: whz1) : (g==1) ? (xp? wxr1: whr1) : (xp? wxh1: whr1);
        const float* p = src + (row*Hh + h)*4;
        float u0=p[0],u1=p[1],u2=p[2],u3=p[3];
        w[0]=u0+u1+u2+u3; w[1]=u0-u2; w[2]=u3-u1; w[3]=u0-u1+u2-u3;
    }
    int base = ((l*3+g)*4)*2048 + c*32 + h;
    #pragma unroll
    for (int s=0;s<4;s++) g_W[base + s*2048] = w[s];
}

// ---------------------------------------------------------------------------
// One-shot fft of ALL timesteps' X -> g_Xall[s][t][n][b*16+f]
// ---------------------------------------------------------------------------
__global__ void xprep_kernel(const float* __restrict__ X){
    int idx = blockIdx.x*blockDim.x + threadIdx.x;
    if (idx >= Tt*Nn*512) return;
    int col = idx & 511;
    int rest = idx >> 9;
    int n = rest % Nn;
    int t = rest / Nn;
    int b = col >> 4, f = col & 15;
    const float4 v = *reinterpret_cast<const float4*>(
        X + ((((size_t)b*Tt + t)*Nn + n)*Ff + f)*4);
    float s1 = v.x - v.z, s2 = v.w - v.y;
    size_t base = (size_t)t*XT + (size_t)n*512 + col;
    const size_t SS = (size_t)Tt*XT;
    g_Xall[0*SS + base] = v.x+v.y+v.z+v.w;
    g_Xall[1*SS + base] = s1;
    g_Xall[2*SS + base] = s2;
    g_Xall[3*SS + base] = v.x-v.y+v.z-v.w;
    g_Xall[4*SS + base] = s1 + s2;
}

// ---------------------------------------------------------------------------
// Aggregation GEMM: Out[s] = A[s] @ B[s]. B split into two regions by column.
// Tile 64x128, threads (32,8), 8x4 per thread, double-buffered smem.
// ---------------------------------------------------------------------------
__global__ __launch_bounds__(256) void agg4_kernel(
    const float* __restrict__ B0, int ld0, size_t sst0, int xlim,
    const float* __restrict__ B1, int ld1, size_t sst1,
    float* __restrict__ Out, int ldo, size_t ssto, int bxOff)
{
    int s = blockIdx.z;
    int colG = (bxOff + blockIdx.x)*128;
    const float* Bp; int ld; size_t sst; int colL;
    if (colG < xlim){ Bp=B0; ld=ld0; sst=sst0; colL=colG; }
    else            { Bp=B1; ld=ld1; sst=sst1; colL=colG-xlim; }
    const float* A = g_At + (size_t)s*NP*NR;
    const float* X = Bp + s*sst + colL;
    float* O = Out + s*ssto + colG;
    int nBase = blockIdx.y*64;

    __shared__ float sA[2][16][64];
    __shared__ float sB[2][16][128];
    int tx=threadIdx.x, ty=threadIdx.y, tid=ty*32+tx;

    int ak = tid>>4, an = (tid&15)*4;
    int bk = tid>>5, bc = (tid&31)*4;
    const float* Ap = A + (size_t)ak*NR + nBase + an;
    const float* Bq = X + (size_t)bk*ld + bc;

    float4 ra, rb0, rb1;
    ra  = *reinterpret_cast<const float4*>(Ap);
    rb0 = *reinterpret_cast<const float4*>(Bq);
    rb1 = *reinterpret_cast<const float4*>(Bq + 8*(size_t)ld);
    *reinterpret_cast<float4*>(&sA[0][ak][an]) = ra;
    *reinterpret_cast<float4*>(&sB[0][bk][bc]) = rb0;
    *reinterpret_cast<float4*>(&sB[0][8+bk][bc]) = rb1;
    __syncthreads();

    float acc[2][4][4] = {};
    for (int ch=0; ch<10; ch++){
        int buf = ch&1;
        if (ch<9){
            size_t ko = (size_t)(ch+1)*16;
            ra  = *reinterpret_cast<const float4*>(Ap + ko*NR);
            rb0 = *reinterpret_cast<const float4*>(Bq + ko*ld);
            rb1 = *reinterpret_cast<const float4*>(Bq + (ko+8)*ld);
        }
        #pragma unroll
        for (int kk=0;kk<16;kk++){
            float4 a0 = *reinterpret_cast<const float4*>(&sA[buf][kk][ty*4]);
            float4 a1 = *reinterpret_cast<const float4*>(&sA[buf][kk][32+ty*4]);
            float4 b  = *reinterpret_cast<const float4*>(&sB[buf][kk][tx*4]);
            float aa0[4]={a0.x,a0.y,a0.z,a0.w};
            float aa1[4]={a1.x,a1.y,a1.z,a1.w};
            float bv[4]={b.x,b.y,b.z,b.w};
            #pragma unroll
            for (int i=0;i<4;i++){
                #pragma unroll
                for (int j=0;j<4;j++){
                    acc[0][i][j] += aa0[i]*bv[j];
                    acc[1][i][j] += aa1[i]*bv[j];
                }
            }
        }
        if (ch<9){
            int nb = buf^1;
            *reinterpret_cast<float4*>(&sA[nb][ak][an]) = ra;
            *reinterpret_cast<float4*>(&sB[nb][bk][bc]) = rb0;
            *reinterpret_cast<float4*>(&sB[nb][8+bk][bc]) = rb1;
        }
        __syncthreads();
    }
    #pragma unroll
    for (int ri=0; ri<2; ri++){
        #pragma unroll
        for (int i=0;i<4;i++){
            int n = nBase + ri*32 + ty*4 + i;
            if (n < Nn)
                *reinterpret_cast<float4*>(O + (size_t)n*ldo + tx*4) =
                    make_float4(acc[ri][i][0],acc[ri][i][1],acc[ri][i][2],acc[ri][i][3]);
        }
    }
}

// ---------------------------------------------------------------------------
// Gates. block (32,4); thread = (h, bt) handles 8 batches. sec = secBase+blockIdx.y
// ---------------------------------------------------------------------------
__global__ void gates4_kernel(int secBase,
    const float* __restrict__ HsA, const float* __restrict__ biasA,
    const float* __restrict__ HsB, const float* __restrict__ biasB)
{
    int n = blockIdx.x;
    int sec = secBase + blockIdx.y;
    const float* Hs   = blockIdx.y ? HsB : HsA;
    const float* bias = blockIdx.y ? biasB : biasA;
    int C    = sec ? 64 : 48;
    int wb   = sec ? 3*8192 : 0;
    int gcol = sec ? 1024 : 0;

    __shared__ float sX[4][64][33];
    int tid = threadIdx.y*32 + threadIdx.x;
    const size_t SS = (size_t)Nn*JB;
    const float* AX = g_AXH + (size_t)n*JB;
    for (int i=tid;i<4*C*32;i+=128){
        int c = i % C; int sb = i / C; int s = sb >> 5; int b = sb & 31;
        int col = (sec==0) ? ((c<16)?(b*16+c):(512 + b*32 + (c-16)))
                           : ((c<32)?(512 + b*32 + c):(1536 + b*32 + (c-32)));
        float v;
        if (s==0)      v = AX[col];
        else if (s==1) v = AX[SS+col] - AX[2*SS+col];
        else if (s==2) v = AX[4*SS+col] - AX[SS+col] - AX[2*SS+col];
        else           v = AX[3*SS+col];
        sX[s][c][b] = v;
    }
    __syncthreads();

    int h = threadIdx.x, bt = threadIdx.y;
    const float* Wz = g_W + wb;
    const float* Wr = Wz + 4*2048;
    float yz0[8]={},yz1[8]={},yz2[8]={},yz3[8]={};
    float yr0[8]={},yr1[8]={},yr2[8]={},yr3[8]={};
    for (int c=0;c<C;c++){
        int wo = c*32 + h;
        float wz0=Wz[wo],wz1=Wz[2048+wo],wz2=Wz[4096+wo],wz3=Wz[6144+wo];
        float wr0=Wr[wo],wr1=Wr[2048+wo],wr2=Wr[4096+wo],wr3=Wr[6144+wo];
        #pragma unroll
        for (int bb=0;bb<8;bb++){
            int b = bt*8+bb;
            float x0=sX[0][c][b], x1r=sX[1][c][b], x1i=sX[2][c][b], x2=sX[3][c][b];
            yz0[bb] += x0*wz0;
            yz1[bb] += x1r*wz1 - x1i*wz2;
            yz2[bb] += x1r*wz2 + x1i*wz1;
            yz3[bb] += x2*wz3;
            yr0[bb] += x0*wr0;
            yr1[bb] += x1r*wr1 - x1i*wr2;
            yr2[bb] += x1r*wr2 + x1i*wr1;
            yr3[bb] += x2*wr3;
        }
    }
    float bz[4], br[4];
    #pragma unroll
    for (int r=0;r<4;r++){ bz[r]=bias[h*4+r]; br[r]=bias[128+h*4+r]; }
    float* Z = g_Z + (size_t)sec*HSZ;
    const size_t GS = (size_t)NP*JG;
    #pragma unroll
    for (int bb=0;bb<8;bb++){
        int b = bt*8+bb;
        float vz[4] = {0.25f*(yz0[bb]+yz3[bb]+2.f*yz1[bb]), 0.25f*(yz0[bb]-yz3[bb]-2.f*yz2[bb]),
                       0.25f*(yz0[bb]+yz3[bb]-2.f*yz1[bb]), 0.25f*(yz0[bb]-yz3[bb]+2.f*yz2[bb])};
        float vr[4] = {0.25f*(yr0[bb]+yr3[bb]+2.f*yr1[bb]), 0.25f*(yr0[bb]-yr3[bb]-2.f*yr2[bb]),
                       0.25f*(yr0[bb]+yr3[bb]-2.f*yr1[bb]), 0.25f*(yr0[bb]-yr3[bb]+2.f*yr2[bb])};
        size_t hoff = (((size_t)b*Nn + n)*Hh + h)*4;
        float4 hs4 = Hs ? *reinterpret_cast<const float4*>(Hs + hoff) : make_float4(0,0,0,0);
        float hsv[4] = {hs4.x,hs4.y,hs4.z,hs4.w};
        float g[4], zv[4];
        #pragma unroll
        for (int r=0;r<4;r++){
            zv[r] = 1.f/(1.f+expf(-(vz[r] + bz[r])));
            float rg = 1.f/(1.f+expf(-(vr[r] + br[r])));
            g[r] = rg*hsv[r];
        }
        *reinterpret_cast<float4*>(Z + hoff) = make_float4(zv[0],zv[1],zv[2],zv[3]);
        size_t gb = (size_t)n*JG + gcol + b*Hh + h;
        float s1 = g[0]-g[2], s2 = g[3]-g[1];
        g_Gf[0*GS + gb] = g[0]+g[1]+g[2]+g[3];
        g_Gf[1*GS + gb] = s1;
        g_Gf[2*GS + gb] = s2;
        g_Gf[3*GS + gb] = g[0]-g[1]+g[2]-g[3];
        g_Gf[4*GS + gb] = s1 + s2;
    }
}

// ---------------------------------------------------------------------------
// Ht + hidden update. Writes new H real, H slot-fft into g_Hf, out and tail.
// ---------------------------------------------------------------------------
__global__ void ht4_kernel(int secBase, int t,
    const float* __restrict__ HsA, const float* __restrict__ biasA,
    float* __restrict__ HnewA, float* __restrict__ outA, float* __restrict__ tailA,
    const float* __restrict__ HsB, const float* __restrict__ biasB,
    float* __restrict__ HnewB, float* __restrict__ outB, float* __restrict__ tailB)
{
    int n = blockIdx.x;
    int sec = secBase + blockIdx.y;
    const float* Hs   = blockIdx.y ? HsB : HsA;
    const float* bias = blockIdx.y ? biasB : biasA;
    float* Hnew = blockIdx.y ? HnewB : HnewA;
    float* outp = blockIdx.y ? outB : outA;
    float* tailp= blockIdx.y ? tailB : tailA;
    int Fin  = sec ? 32 : 16;
    int wb   = sec ? 5*8192 : 2*8192;
    int gcol = sec ? 1024 : 0;
    int hbase= sec ? 1024 : 0;

    __shared__ float sXx[4][32][33];
    __shared__ float sG[4][32][33];
    int tid = threadIdx.y*32 + threadIdx.x;
    const size_t SS = (size_t)Nn*JB;
    const size_t AS = (size_t)Nn*JG;
    const float* AX = g_AXH + (size_t)n*JB;
    const float* AG = g_AG + (size_t)n*JG + gcol;
    for (int i=tid;i<4*Fin*32;i+=128){
        int c = i % Fin; int sb = i / Fin; int s = sb >> 5; int b = sb & 31;
        int col = (sec==0) ? (b*16+c) : (512 + b*32 + c);
        float v;
        if (s==0)      v = AX[col];
        else if (s==1) v = AX[SS+col] - AX[2*SS+col];
        else if (s==2) v = AX[4*SS+col] - AX[SS+col] - AX[2*SS+col];
        else           v = AX[3*SS+col];
        sXx[s][c][b] = v;
    }
    for (int i=tid;i<4*32*32;i+=128){
        int c = i & 31; int sb = i >> 5; int s = sb >> 5; int b = sb & 31;
        int col = b*Hh + c;
        float v;
        if (s==0)      v = AG[col];
        else if (s==1) v = AG[AS+col] - AG[2*AS+col];
        else if (s==2) v = AG[4*AS+col] - AG[AS+col] - AG[2*AS+col];
        else           v = AG[3*AS+col];
        sG[s][c][b] = v;
    }
    __syncthreads();

    int h = threadIdx.x, bt = threadIdx.y;
    const float* Wh = g_W + wb;
    float y0[8]={},y1[8]={},y2[8]={},y3[8]={};
    for (int c=0;c<Fin;c++){
        int wo = c*32 + h;
        float w0=Wh[wo],w1=Wh[2048+wo],w2=Wh[4096+wo],w3=Wh[6144+wo];
        #pragma unroll
        for (int bb=0;bb<8;bb++){
            int b = bt*8+bb;
            float x0=sXx[0][c][b], x1r=sXx[1][c][b], x1i=sXx[2][c][b], x2=sXx[3][c][b];
            y0[bb] += x0*w0;
            y1[bb] += x1r*w1 - x1i*w2;
            y2[bb] += x1r*w2 + x1i*w1;
            y3[bb] += x2*w3;
        }
    }
    for (int c=0;c<Hh;c++){
        int wo = (Fin+c)*32 + h;
        float w0=Wh[wo],w1=Wh[2048+wo],w2=Wh[4096+wo],w3=Wh[6144+wo];
        #pragma unroll
        for (int bb=0;bb<8;bb++){
            int b = bt*8+bb;
            float x0=sG[0][c][b], x1r=sG[1][c][b], x1i=sG[2][c][b], x2=sG[3][c][b];
            y0[bb] += x0*w0;
            y1[bb] += x1r*w1 - x1i*w2;
            y2[bb] += x1r*w2 + x1i*w1;
            y3[bb] += x2*w3;
        }
    }
    float bh[4];
    #pragma unroll
    for (int r=0;r<4;r++) bh[r] = bias[256 + h*4 + r];
    const float* Z = g_Z + (size_t)sec*HSZ;
    const size_t HS = (size_t)NP*JG;
    #pragma unroll
    for (int bb=0;bb<8;bb++){
        int b = bt*8+bb;
        float v[4] = {0.25f*(y0[bb]+y3[bb]+2.f*y1[bb]), 0.25f*(y0[bb]-y3[bb]-2.f*y2[bb]),
                      0.25f*(y0[bb]+y3[bb]-2.f*y1[bb]), 0.25f*(y0[bb]-y3[bb]+2.f*y2[bb])};
        size_t hoff = (((size_t)b*Nn+n)*Hh + h)*4;
        float4 z4 = *reinterpret_cast<const float4*>(Z + hoff);
        float zv[4] = {z4.x,z4.y,z4.z,z4.w};
        float4 hs4 = Hs ? *reinterpret_cast<const float4*>(Hs + hoff) : make_float4(0,0,0,0);
        float hsv[4] = {hs4.x,hs4.y,hs4.z,hs4.w};
        float hn[4];
        #pragma unroll
        for (int r=0;r<4;r++){
            float ht = tanhf(v[r] + bh[r]);
            hn[r] = zv[r]*hsv[r] + (1.f-zv[r])*ht;
        }
        float4 hv = make_float4(hn[0],hn[1],hn[2],hn[3]);
        *reinterpret_cast<float4*>(Hnew + hoff) = hv;
        if (outp)
            *reinterpret_cast<float4*>(outp + (((size_t)b*Tt + t)*Nn + n)*(Hh*4) + h*4) = hv;
        if (tailp)
            *reinterpret_cast<float4*>(tailp + hoff) = hv;
        // slot-fft of new hidden -> g_Hf for next step's aggregation
        size_t hb = (size_t)n*JG + hbase + b*Hh + h;
        float s1 = hn[0]-hn[2], s2 = hn[3]-hn[1];
        g_Hf[0*HS + hb] = hn[0]+hn[1]+hn[2]+hn[3];
        g_Hf[1*HS + hb] = s1;
        g_Hf[2*HS + hb] = s2;
        g_Hf[3*HS + hb] = hn[0]-hn[1]+hn[2]-hn[3];
        g_Hf[4*HS + hb] = s1 + s2;
    }
}

// ---------------------------------------------------------------------------
extern "C" void kernel_launch(void* const* d_in, const int* in_sizes, int n_in,
                              void* d_out, int out_size) {
    (void)in_sizes; (void)n_in;
    const float* inputs = (const float*)d_in[0];
    const float* U      = (const float*)d_in[1];
    const float* B0p    = (const float*)d_in[7];
    const float* B1p    = (const float*)d_in[13];
    float* out = (float*)d_out;
    const int OUTSZ = Bb*Tt*Nn*Hh*Rr;
    float* tail = (out_size >= OUTSZ + 2*HSZ) ? (out + OUTSZ) : nullptr;

    void* p;
    cudaGetSymbolAddress(&p, g_At);   float* Atp  = (float*)p;
    cudaGetSymbolAddress(&p, g_Xall); float* Xall = (float*)p;
    cudaGetSymbolAddress(&p, g_Hf);   float* Hf   = (float*)p;
    cudaGetSymbolAddress(&p, g_AXH);  float* AXH  = (float*)p;
    cudaGetSymbolAddress(&p, g_Gf);   float* Gfp  = (float*)p;
    cudaGetSymbolAddress(&p, g_AG);   float* AG   = (float*)p;
    cudaGetSymbolAddress(&p, g_H);    float* Hb   = (float*)p;
    float* H0[2] = {Hb,          Hb +   HSZ};
    float* H1[2] = {Hb + 2*HSZ,  Hb + 3*HSZ};

    cudaMemsetAsync(Atp,  0, sizeof(float)*5*NP*NR);
    cudaMemsetAsync(Xall, 0, sizeof(float)*5*Tt*NP*512);
    cudaMemsetAsync(Hf,   0, sizeof(float)*5*NP*JG);
    cudaMemsetAsync(Gfp,  0, sizeof(float)*5*NP*JG);
    cudaMemsetAsync(AG,   0, sizeof(float)*5*Nn*JG);
    cudaMemsetAsync(AXH,  0, sizeof(float)*5*Nn*JB);

    adj_kernel<<<Nn, 256>>>(U);
    wprep_kernel<<<48, 256>>>((const float*)d_in[2], (const float*)d_in[3], (const float*)d_in[4],
                              (const float*)d_in[5], (const float*)d_in[6],
                              (const float*)d_in[8], (const float*)d_in[9], (const float*)d_in[10],
                              (const float*)d_in[11], (const float*)d_in[12]);
    xprep_kernel<<<(Tt*Nn*512+255)/256, 256>>>(inputs);

    const size_t XSST = (size_t)Tt*XT;
    const size_t HSST = (size_t)NP*JG;
    const size_t AXS  = (size_t)Nn*JB;
    const size_t AGS  = (size_t)Nn*JG;
    dim3 blk128(32,4);
    dim3 aggT(32,8);

    // ---- t = 0 ----
    // layer0: X cols only (H cols of AXH are zero via memset; Hf is zero anyway)
    agg4_kernel<<<dim3(4,3,5), aggT>>>(Xall, 512, XSST, 512, Hf, JG, HSST, AXH, JB, AXS, 0);
    gates4_kernel<<<dim3(Nn,1), blk128>>>(0, nullptr, B0p, nullptr, B0p);
    ht4_kernel<<<dim3(Nn,1), blk128>>>(0, 0,
        nullptr, B0p, H0[1], nullptr, nullptr,
        nullptr, B0p, H0[1], nullptr, nullptr);
    // aggregate A @ fft(H0(t0)) for layer1's t0 input (H1 part stays zero)
    agg4_kernel<<<dim3(8,3,5), aggT>>>(Xall, 512, XSST, 512, Hf, JG, HSST, AXH, JB, AXS, 4);
    gates4_kernel<<<dim3(Nn,1), blk128>>>(1, nullptr, B1p, nullptr, B1p);
    ht4_kernel<<<dim3(Nn,1), blk128>>>(1, 0,
        nullptr, B1p, H1[1], out, nullptr,
        nullptr, B1p, H1[1], out, nullptr);

    // ---- t = 1..7 ----
    int c0 = 1, c1 = 1;
    for (int t=1; t<Tt; t++){
        float* tl0 = (t==Tt-1 && tail) ? tail        : nullptr;
        float* tl1 = (t==Tt-1 && tail) ? tail + HSZ  : nullptr;
        const float* Xt = Xall + (size_t)t*XT;
        agg4_kernel<<<dim3(20,3,5), aggT>>>(Xt, 512, XSST, 512, Hf, JG, HSST, AXH, JB, AXS, 0);
        gates4_kernel<<<dim3(Nn,2), blk128>>>(0, H0[c0], B0p, H1[c1], B1p);
        agg4_kernel<<<dim3(16,3,5), aggT>>>(Gfp, JG, HSST, 1<<30, Gfp, JG, HSST, AG, JG, AGS, 0);
        ht4_kernel<<<dim3(Nn,2), blk128>>>(0, t,
            H0[c0], B0p, H0[c0^1], nullptr, tl0,
            H1[c1], B1p, H1[c1^1], out,     tl1);
        c0 ^= 1; c1 ^= 1;
    }
}